// round 1
// baseline (speedup 1.0000x reference)
#include <cuda_runtime.h>
#include <cstdint>

// Problem constants
#define NN     116
#define FIN    116
#define HIDD   256
#define OUT2   4
#define RDIM   64
#define OUTC   2

#define PA     120   // pitch (floats) for s_x / s_sup, K padded to 120
#define PXW    132   // pitch for s_xw (avoids bank alignment of 8-row strides)
#define NSTAGE 15    // 15 * 8 = 120 K-steps for GEMM1

// SMEM layout (floats)
#define OFF_X     0
#define OFF_SUP   (OFF_X   + 128*PA)        // 15360
#define OFF_XW    (OFF_SUP + 128*PA)        // 30720
#define OFF_WB    (OFF_XW  + 128*PXW)       // 47616
#define OFF_W2    (OFF_WB  + 2*8*128)       // 49664
#define OFF_B1    (OFF_W2  + HIDD*OUT2)     // 50688
#define OFF_Z     (OFF_B1  + HIDD)          // 50944
#define OFF_FLAT  (OFF_Z   + 128*OUT2)      // 51456
#define OFF_RP    (OFF_FLAT+ 480)           // 51936
#define OFF_R     (OFF_RP  + 256)           // 52192
#define OFF_RED   (OFF_R   + 64)            // 52256
#define SMEM_FLOATS (OFF_RED + 16)          // 52272 floats = 209088 B

extern __shared__ float smem[];

// ---- packed fp32x2 helpers (full-rate FMA path on sm_103a) ----
__device__ __forceinline__ uint64_t pack2(float lo, float hi) {
    uint64_t r;
    asm("mov.b64 %0, {%1, %2};" : "=l"(r) : "f"(lo), "f"(hi));
    return r;
}
__device__ __forceinline__ float2 unpack2(uint64_t v) {
    float2 f;
    asm("mov.b64 {%0, %1}, %2;" : "=f"(f.x), "=f"(f.y) : "l"(v));
    return f;
}
__device__ __forceinline__ void fma2(uint64_t& d, uint64_t a, uint64_t b) {
    asm("fma.rn.f32x2 %0, %1, %2, %0;" : "+l"(d) : "l"(a), "l"(b));
}

// ---- cp.async helpers ----
__device__ __forceinline__ void cpasync16(void* s, const void* g) {
    uint32_t sa = (uint32_t)__cvta_generic_to_shared(s);
    asm volatile("cp.async.cg.shared.global [%0], [%1], 16;" :: "r"(sa), "l"(g));
}
#define CP_COMMIT() asm volatile("cp.async.commit_group;")
#define CP_WAIT(n)  asm volatile("cp.async.wait_group %0;" :: "n"(n))

__global__ void __launch_bounds__(256, 1) gcn_fused(
    const float* __restrict__ x,   const float* __restrict__ sup,
    const float* __restrict__ W1,  const float* __restrict__ b1,
    const float* __restrict__ W2,  const float* __restrict__ b2,
    const float* __restrict__ Wr1, const float* __restrict__ br1,
    const float* __restrict__ Wr2, const float* __restrict__ br2,
    float* __restrict__ out)
{
    float* s_x    = smem + OFF_X;
    float* s_sup  = smem + OFF_SUP;
    float* s_xw   = smem + OFF_XW;
    float* s_wb   = smem + OFF_WB;
    float* s_w2   = smem + OFF_W2;
    float* s_b1   = smem + OFF_B1;
    float* s_z    = smem + OFF_Z;
    float* s_flat = smem + OFF_FLAT;
    float* s_rp   = smem + OFF_RP;
    float* s_r    = smem + OFF_R;
    float* s_red  = smem + OFF_RED;

    const int tid = threadIdx.x;
    const int b   = blockIdx.x;

    // ---- zero pads + preload small weights ----
    for (int i = tid; i < 128 * PA; i += 256) { s_x[i] = 0.f; s_sup[i] = 0.f; }
    for (int i = tid; i < 128 * OUT2; i += 256) s_z[i] = 0.f;
    for (int i = tid; i < HIDD * OUT2; i += 256) s_w2[i] = W2[i];
    for (int i = tid; i < HIDD; i += 256) s_b1[i] = b1[i];
    __syncthreads();

    // ---- load x[b], support[b] (float4 coalesced; 116 = 29*4) ----
    const float* xb = x   + (size_t)b * NN * FIN;
    const float* sb = sup + (size_t)b * NN * NN;
    for (int q = tid; q < NN * 29; q += 256) {
        int row = q / 29, c4 = (q % 29) * 4;
        *(float4*)&s_x[row * PA + c4]   = *(const float4*)&xb[row * FIN + c4];
        *(float4*)&s_sup[row * PA + c4] = *(const float4*)&sb[row * NN  + c4];
    }
    __syncthreads();

    const int tx = tid & 15, ty = tid >> 4;
    const int r0 = ty * 8, c0 = tx * 8;

    const int wr = tid >> 5;          // 0..7  (stage row)
    const int wc = (tid & 31) * 4;    // 0..124 (stage float4 col)

    for (int half = 0; half < 2; ++half) {
        // ================= GEMM1: xw = x @ W1[:, half*128 : +128] =================
        uint64_t acc[8][4];
        #pragma unroll
        for (int i = 0; i < 8; i++)
            #pragma unroll
            for (int j = 0; j < 4; j++) acc[i][j] = 0ull;

        // prologue: stage 0
        {
            int k = wr;
            if (k < FIN) cpasync16(&s_wb[wr * 128 + wc], &W1[k * HIDD + half * 128 + wc]);
            else *(float4*)&s_wb[wr * 128 + wc] = make_float4(0.f, 0.f, 0.f, 0.f);
        }
        CP_COMMIT();

        for (int s = 0; s < NSTAGE; ++s) {
            const float* wb = s_wb + (s & 1) * 1024;
            if (s + 1 < NSTAGE) {
                float* wbn = s_wb + ((s + 1) & 1) * 1024;
                int k = (s + 1) * 8 + wr;
                if (k < FIN) cpasync16(&wbn[wr * 128 + wc], &W1[k * HIDD + half * 128 + wc]);
                else *(float4*)&wbn[wr * 128 + wc] = make_float4(0.f, 0.f, 0.f, 0.f);
                CP_COMMIT();
                CP_WAIT(1);
            } else {
                CP_WAIT(0);
            }
            __syncthreads();

            const int k0 = s * 8;
            #pragma unroll
            for (int kk = 0; kk < 8; ++kk) {
                const float* br = &wb[kk * 128 + c0];
                ulonglong2 bA = *(const ulonglong2*)br;
                ulonglong2 bB = *(const ulonglong2*)(br + 4);
                #pragma unroll
                for (int i = 0; i < 8; i++) {
                    float a = s_x[(r0 + i) * PA + k0 + kk];
                    uint64_t a2 = pack2(a, a);
                    fma2(acc[i][0], a2, bA.x);
                    fma2(acc[i][1], a2, bA.y);
                    fma2(acc[i][2], a2, bB.x);
                    fma2(acc[i][3], a2, bB.y);
                }
            }
            __syncthreads();
        }

        // write xw half to SMEM
        #pragma unroll
        for (int i = 0; i < 8; i++) {
            ulonglong2* dst = (ulonglong2*)&s_xw[(r0 + i) * PXW + c0];
            ulonglong2 v0; v0.x = acc[i][0]; v0.y = acc[i][1];
            ulonglong2 v1; v1.x = acc[i][2]; v1.y = acc[i][3];
            dst[0] = v0; dst[1] = v1;
        }
        __syncthreads();

        // ===== GEMM2: h1 = relu(sup @ xw + b1); fused z += h1 @ W2[half] =====
        #pragma unroll
        for (int i = 0; i < 8; i++)
            #pragma unroll
            for (int j = 0; j < 4; j++) acc[i][j] = 0ull;

        #pragma unroll 4
        for (int k = 0; k < NN; ++k) {
            const float* br = &s_xw[k * PXW + c0];
            ulonglong2 bA = *(const ulonglong2*)br;
            ulonglong2 bB = *(const ulonglong2*)(br + 4);
            #pragma unroll
            for (int i = 0; i < 8; i++) {
                float a = s_sup[(r0 + i) * PA + k];
                uint64_t a2 = pack2(a, a);
                fma2(acc[i][0], a2, bA.x);
                fma2(acc[i][1], a2, bA.y);
                fma2(acc[i][2], a2, bB.x);
                fma2(acc[i][3], a2, bB.y);
            }
        }

        // epilogue: relu(+b1), contract with W2 into z partials
        float zp[8][4];
        #pragma unroll
        for (int i = 0; i < 8; i++)
            #pragma unroll
            for (int o = 0; o < 4; o++) zp[i][o] = 0.f;

        #pragma unroll
        for (int i = 0; i < 8; i++) {
            #pragma unroll
            for (int jj = 0; jj < 4; jj++) {
                float2 v = unpack2(acc[i][jj]);
                int cg = half * 128 + c0 + jj * 2;
                float h0 = fmaxf(v.x + s_b1[cg],     0.f);
                float h1 = fmaxf(v.y + s_b1[cg + 1], 0.f);
                #pragma unroll
                for (int o = 0; o < 4; o++)
                    zp[i][o] += h0 * s_w2[cg * 4 + o] + h1 * s_w2[(cg + 1) * 4 + o];
            }
        }
        // reduce across the 16 threads (tx) sharing the same rows (lanes 0-15 / 16-31)
        #pragma unroll
        for (int i = 0; i < 8; i++) {
            #pragma unroll
            for (int o = 0; o < 4; o++) {
                float v = zp[i][o];
                v += __shfl_xor_sync(0xffffffffu, v, 1);
                v += __shfl_xor_sync(0xffffffffu, v, 2);
                v += __shfl_xor_sync(0xffffffffu, v, 4);
                v += __shfl_xor_sync(0xffffffffu, v, 8);
                if (tx == 0) s_z[(r0 + i) * 4 + o] += v;
            }
        }
        __syncthreads();
    } // half

    // ===== h2 = relu(sup @ z + b2) -> flat[464] =====
    for (int idx = tid; idx < NN * OUT2; idx += 256) {
        int m = idx >> 2, o = idx & 3;
        float a0 = 0.f, a1 = 0.f;
        #pragma unroll 4
        for (int j = 0; j < NN; j += 2) {
            a0 += s_sup[m * PA + j]     * s_z[j * 4 + o];
            a1 += s_sup[m * PA + j + 1] * s_z[(j + 1) * 4 + o];
        }
        s_flat[idx] = fmaxf(a0 + a1 + b2[o], 0.f);
    }
    __syncthreads();

    // ===== r = relu(flat @ Wr1 + br1) : 464x64, 4 partial threads per output =====
    {
        int j = tid & 63, p = tid >> 6;   // p in 0..3, each covers 116 rows
        int i0 = p * 116;
        float a0 = 0.f, a1 = 0.f;
        #pragma unroll 4
        for (int i = 0; i < 116; i += 2) {
            a0 += s_flat[i0 + i]     * Wr1[(size_t)(i0 + i)     * 64 + j];
            a1 += s_flat[i0 + i + 1] * Wr1[(size_t)(i0 + i + 1) * 64 + j];
        }
        s_rp[p * 64 + j] = a0 + a1;
    }
    __syncthreads();
    if (tid < 64) {
        float v = s_rp[tid] + s_rp[64 + tid] + s_rp[128 + tid] + s_rp[192 + tid] + br1[tid];
        s_r[tid] = fmaxf(v, 0.f);
    }
    __syncthreads();

    // ===== logits = r @ Wr2 + br2 ; log_softmax (2 classes) =====
    if (tid < 64) {
        float rv = s_r[tid];
        float p0 = rv * Wr2[tid * 2 + 0];
        float p1 = rv * Wr2[tid * 2 + 1];
        #pragma unroll
        for (int m = 16; m >= 1; m >>= 1) {
            p0 += __shfl_xor_sync(0xffffffffu, p0, m);
            p1 += __shfl_xor_sync(0xffffffffu, p1, m);
        }
        if ((tid & 31) == 0) {
            s_red[(tid >> 5) * 2 + 0] = p0;
            s_red[(tid >> 5) * 2 + 1] = p1;
        }
    }
    __syncthreads();
    if (tid == 0) {
        float l0 = s_red[0] + s_red[2] + br2[0];
        float l1 = s_red[1] + s_red[3] + br2[1];
        float mx = fmaxf(l0, l1);
        float lse = mx + logf(expf(l0 - mx) + expf(l1 - mx));
        out[(size_t)b * 2 + 0] = l0 - lse;
        out[(size_t)b * 2 + 1] = l1 - lse;
    }
}

extern "C" void kernel_launch(void* const* d_in, const int* in_sizes, int n_in,
                              void* d_out, int out_size) {
    const float* x   = (const float*)d_in[0];
    const float* sup = (const float*)d_in[1];
    const float* W1  = (const float*)d_in[2];
    const float* b1  = (const float*)d_in[3];
    const float* W2  = (const float*)d_in[4];
    const float* b2  = (const float*)d_in[5];
    const float* Wr1 = (const float*)d_in[6];
    const float* br1 = (const float*)d_in[7];
    const float* Wr2 = (const float*)d_in[8];
    const float* br2 = (const float*)d_in[9];
    float* out = (float*)d_out;

    int B = in_sizes[0] / (NN * FIN);

    size_t shmem = (size_t)SMEM_FLOATS * sizeof(float);
    cudaFuncSetAttribute(gcn_fused, cudaFuncAttributeMaxDynamicSharedMemorySize, (int)shmem);
    gcn_fused<<<B, 256, shmem>>>(x, sup, W1, b1, W2, b2, Wr1, br1, Wr2, br2, out);
}

// round 2
// speedup vs baseline: 1.2596x; 1.2596x over previous
#include <cuda_runtime.h>
#include <cstdint>

// Problem constants
#define NN     116
#define FIN    116
#define HIDD   256
#define OUT2   4
#define PX     132    // smem row pitch (floats)

// SMEM layout (floats)
#define OFF_XT    0                         // x^T  [116][PX]  (zero-padded cols 116..127)
#define OFF_SUPT  15360                     // sup^T[116][PX]
#define OFF_BW    30720                     // W1-half staging / xw  [128][PX]
#define OFF_W2    47616                     // W2 [256][4]
#define OFF_B1    48640                     // b1 [256]
#define OFF_Z     48896                     // z  [128][4]
#define OFF_FLAT  49408                     // flat [464] (pad 480)
#define OFF_RP    49888                     // readout partials [512]
#define OFF_R     50400                     // r [64]
#define OFF_RED   50464                     // final reduce [16]
#define SMEM_FLOATS 50480                   // 201920 bytes

extern __shared__ float smem[];

// ---- packed fp32x2 helpers ----
__device__ __forceinline__ uint64_t pack2(float lo, float hi) {
    uint64_t r;
    asm("mov.b64 %0, {%1, %2};" : "=l"(r) : "f"(lo), "f"(hi));
    return r;
}
__device__ __forceinline__ float2 unpack2(uint64_t v) {
    float2 f;
    asm("mov.b64 {%0, %1}, %2;" : "=f"(f.x), "=f"(f.y) : "l"(v));
    return f;
}
__device__ __forceinline__ void fma2(uint64_t& d, uint64_t a, uint64_t b) {
    asm("fma.rn.f32x2 %0, %1, %2, %0;" : "+l"(d) : "l"(a), "l"(b));
}

// 8 rows (r0..r0+7, packed as 4 f32x2 pairs from A^T) x 4 cols (c0..c0+3)
__device__ __forceinline__ void gemm_8x4(uint64_t acc[4][4],
                                         const float* __restrict__ At,
                                         const float* __restrict__ Bm,
                                         int r0, int c0)
{
    #pragma unroll 4
    for (int k = 0; k < NN; ++k) {
        ulonglong2 a01 = *(const ulonglong2*)&At[k * PX + r0];      // rows r0..r0+3
        ulonglong2 a23 = *(const ulonglong2*)&At[k * PX + r0 + 4];  // rows r0+4..r0+7
        float4 bv = *(const float4*)&Bm[k * PX + c0];
        uint64_t b0 = pack2(bv.x, bv.x);
        uint64_t b1 = pack2(bv.y, bv.y);
        uint64_t b2 = pack2(bv.z, bv.z);
        uint64_t b3 = pack2(bv.w, bv.w);
        fma2(acc[0][0], a01.x, b0); fma2(acc[0][1], a01.x, b1);
        fma2(acc[0][2], a01.x, b2); fma2(acc[0][3], a01.x, b3);
        fma2(acc[1][0], a01.y, b0); fma2(acc[1][1], a01.y, b1);
        fma2(acc[1][2], a01.y, b2); fma2(acc[1][3], a01.y, b3);
        fma2(acc[2][0], a23.x, b0); fma2(acc[2][1], a23.x, b1);
        fma2(acc[2][2], a23.x, b2); fma2(acc[2][3], a23.x, b3);
        fma2(acc[3][0], a23.y, b0); fma2(acc[3][1], a23.y, b1);
        fma2(acc[3][2], a23.y, b2); fma2(acc[3][3], a23.y, b3);
    }
}

__global__ void __launch_bounds__(512, 1) gcn_fused(
    const float* __restrict__ x,   const float* __restrict__ sup,
    const float* __restrict__ W1,  const float* __restrict__ b1,
    const float* __restrict__ W2,  const float* __restrict__ b2,
    const float* __restrict__ Wr1, const float* __restrict__ br1,
    const float* __restrict__ Wr2, const float* __restrict__ br2,
    float* __restrict__ out)
{
    float* s_xT   = smem + OFF_XT;
    float* s_supT = smem + OFF_SUPT;
    float* s_bw   = smem + OFF_BW;     // W1-half, later xw (overlaid)
    float* s_w2   = smem + OFF_W2;
    float* s_b1   = smem + OFF_B1;
    float* s_z    = smem + OFF_Z;
    float* s_flat = smem + OFF_FLAT;
    float* s_rp   = smem + OFF_RP;
    float* s_r    = smem + OFF_R;
    float* s_red  = smem + OFF_RED;

    const int tid  = threadIdx.x;
    const int b    = blockIdx.x;
    const int lane = tid & 31;
    const int warp = tid >> 5;          // 0..15
    const int r0   = warp * 8;          // 8 rows per warp (128 rows)
    const int c0   = lane * 4;          // 4 cols per lane (128 cols)

    // ---- zero pads + preload small weights ----
    for (int i = tid; i < NN * PX; i += 512) { s_xT[i] = 0.f; s_supT[i] = 0.f; }
    for (int i = tid; i < 128 * OUT2; i += 512) s_z[i] = 0.f;
    for (int i = tid; i < HIDD * OUT2; i += 512) s_w2[i] = W2[i];
    for (int i = tid; i < HIDD; i += 512) s_b1[i] = b1[i];
    __syncthreads();

    // ---- load x[b], support[b], storing TRANSPOSED (coalesced global reads) ----
    const float* xb = x   + (size_t)b * NN * FIN;
    const float* sb = sup + (size_t)b * NN * NN;
    for (int q = tid; q < NN * 29; q += 512) {
        int m = q / 29, k4 = (q % 29) * 4;
        float4 vx = *(const float4*)&xb[m * FIN + k4];
        float4 vs = *(const float4*)&sb[m * NN  + k4];
        s_xT[(k4+0) * PX + m] = vx.x; s_xT[(k4+1) * PX + m] = vx.y;
        s_xT[(k4+2) * PX + m] = vx.z; s_xT[(k4+3) * PX + m] = vx.w;
        s_supT[(k4+0) * PX + m] = vs.x; s_supT[(k4+1) * PX + m] = vs.y;
        s_supT[(k4+2) * PX + m] = vs.z; s_supT[(k4+3) * PX + m] = vs.w;
    }
    __syncthreads();

    for (int half = 0; half < 2; ++half) {
        // ---- stage W1[:, half*128 : +128] fully into s_bw ----
        for (int q = tid; q < NN * 32; q += 512) {
            int k = q >> 5, c4 = (q & 31) * 4;
            *(float4*)&s_bw[k * PX + c4] =
                *(const float4*)&W1[k * HIDD + half * 128 + c4];
        }
        __syncthreads();

        // ================= GEMM1: xw = x @ W1half =================
        uint64_t acc[4][4];
        #pragma unroll
        for (int i = 0; i < 4; i++)
            #pragma unroll
            for (int j = 0; j < 4; j++) acc[i][j] = 0ull;

        gemm_8x4(acc, s_xT, s_bw, r0, c0);
        __syncthreads();   // all W1 reads done

        // write xw into the same buffer (row-major [M][PX])
        #pragma unroll
        for (int rp = 0; rp < 4; ++rp) {
            float2 p0 = unpack2(acc[rp][0]);
            float2 p1 = unpack2(acc[rp][1]);
            float2 p2 = unpack2(acc[rp][2]);
            float2 p3 = unpack2(acc[rp][3]);
            float4 v0 = make_float4(p0.x, p1.x, p2.x, p3.x);  // row r0+2rp
            float4 v1 = make_float4(p0.y, p1.y, p2.y, p3.y);  // row r0+2rp+1
            *(float4*)&s_bw[(r0 + 2*rp    ) * PX + c0] = v0;
            *(float4*)&s_bw[(r0 + 2*rp + 1) * PX + c0] = v1;
        }
        __syncthreads();

        // ===== GEMM2: h1 = relu(sup @ xw + b1); fused z += h1 @ W2half =====
        #pragma unroll
        for (int i = 0; i < 4; i++)
            #pragma unroll
            for (int j = 0; j < 4; j++) acc[i][j] = 0ull;

        gemm_8x4(acc, s_supT, s_bw, r0, c0);

        // epilogue: bias+relu, contract with W2 -> z partials
        float zp[8][4];
        #pragma unroll
        for (int i = 0; i < 8; i++)
            #pragma unroll
            for (int o = 0; o < 4; o++) zp[i][o] = 0.f;

        #pragma unroll
        for (int rp = 0; rp < 4; ++rp) {
            #pragma unroll
            for (int j = 0; j < 4; ++j) {
                float2 v = unpack2(acc[rp][j]);
                int col = half * 128 + c0 + j;
                float bias = s_b1[col];
                float h0 = fmaxf(v.x + bias, 0.f);   // row r0+2rp
                float h1 = fmaxf(v.y + bias, 0.f);   // row r0+2rp+1
                #pragma unroll
                for (int o = 0; o < 4; o++) {
                    float w = s_w2[col * 4 + o];
                    zp[2*rp    ][o] += h0 * w;
                    zp[2*rp + 1][o] += h1 * w;
                }
            }
        }
        // reduce over the 32 lanes (cols) of this warp
        #pragma unroll
        for (int i = 0; i < 8; i++) {
            #pragma unroll
            for (int o = 0; o < 4; o++) {
                float v = zp[i][o];
                v += __shfl_xor_sync(0xffffffffu, v, 16);
                v += __shfl_xor_sync(0xffffffffu, v, 8);
                v += __shfl_xor_sync(0xffffffffu, v, 4);
                v += __shfl_xor_sync(0xffffffffu, v, 2);
                v += __shfl_xor_sync(0xffffffffu, v, 1);
                if (lane == 0) s_z[(r0 + i) * 4 + o] += v;
            }
        }
        __syncthreads();
    } // half

    // ===== h2 = relu(sup @ z + b2) -> flat[464] =====
    if (tid < NN * OUT2) {
        int m = tid >> 2, o = tid & 3;
        float a0 = 0.f, a1 = 0.f;
        #pragma unroll 4
        for (int j = 0; j < NN; j += 2) {
            a0 += s_supT[j * PX + m]       * s_z[j * 4 + o];
            a1 += s_supT[(j + 1) * PX + m] * s_z[(j + 1) * 4 + o];
        }
        s_flat[tid] = fmaxf(a0 + a1 + b2[o], 0.f);
    }
    __syncthreads();

    // ===== r = relu(flat @ Wr1 + br1) : 464x64, 8 partials per output =====
    {
        int j = tid & 63, p = tid >> 6;   // p in 0..7, 58 rows each
        int i0 = p * 58;
        float a0 = 0.f, a1 = 0.f;
        #pragma unroll 2
        for (int i = 0; i < 58; i += 2) {
            a0 += s_flat[i0 + i]     * Wr1[(size_t)(i0 + i)     * 64 + j];
            a1 += s_flat[i0 + i + 1] * Wr1[(size_t)(i0 + i + 1) * 64 + j];
        }
        s_rp[p * 64 + j] = a0 + a1;
    }
    __syncthreads();
    if (tid < 64) {
        float v = br1[tid];
        #pragma unroll
        for (int p = 0; p < 8; p++) v += s_rp[p * 64 + tid];
        s_r[tid] = fmaxf(v, 0.f);
    }
    __syncthreads();

    // ===== logits = r @ Wr2 + br2 ; log_softmax (2 classes) =====
    if (tid < 64) {
        float rv = s_r[tid];
        float p0 = rv * Wr2[tid * 2 + 0];
        float p1 = rv * Wr2[tid * 2 + 1];
        #pragma unroll
        for (int m = 16; m >= 1; m >>= 1) {
            p0 += __shfl_xor_sync(0xffffffffu, p0, m);
            p1 += __shfl_xor_sync(0xffffffffu, p1, m);
        }
        if ((tid & 31) == 0) {
            s_red[(tid >> 5) * 2 + 0] = p0;
            s_red[(tid >> 5) * 2 + 1] = p1;
        }
    }
    __syncthreads();
    if (tid == 0) {
        float l0 = s_red[0] + s_red[2] + br2[0];
        float l1 = s_red[1] + s_red[3] + br2[1];
        float mx = fmaxf(l0, l1);
        float lse = mx + logf(expf(l0 - mx) + expf(l1 - mx));
        out[(size_t)b * 2 + 0] = l0 - lse;
        out[(size_t)b * 2 + 1] = l1 - lse;
    }
}

extern "C" void kernel_launch(void* const* d_in, const int* in_sizes, int n_in,
                              void* d_out, int out_size) {
    const float* x   = (const float*)d_in[0];
    const float* sup = (const float*)d_in[1];
    const float* W1  = (const float*)d_in[2];
    const float* b1  = (const float*)d_in[3];
    const float* W2  = (const float*)d_in[4];
    const float* b2  = (const float*)d_in[5];
    const float* Wr1 = (const float*)d_in[6];
    const float* br1 = (const float*)d_in[7];
    const float* Wr2 = (const float*)d_in[8];
    const float* br2 = (const float*)d_in[9];
    float* out = (float*)d_out;

    int B = in_sizes[0] / (NN * FIN);

    size_t shmem = (size_t)SMEM_FLOATS * sizeof(float);
    cudaFuncSetAttribute(gcn_fused, cudaFuncAttributeMaxDynamicSharedMemorySize, (int)shmem);
    gcn_fused<<<B, 512, shmem>>>(x, sup, W1, b1, W2, b2, Wr1, br1, Wr2, br2, out);
}

// round 4
// speedup vs baseline: 1.7485x; 1.3882x over previous
#include <cuda_runtime.h>
#include <cuda_bf16.h>
#include <cstdint>

#define NN   116
#define FIN  116
#define HIDD 256
#define PITCH 136                       // bf16 elems per tile row (272B, 17x16B)
#define TILE_BYTES (128 * PITCH * 2)    // 34816

// ---- SMEM byte offsets ----
#define OFF_XHI   0
#define OFF_XLO   (OFF_XHI + TILE_BYTES)
#define OFF_SHI   (OFF_XLO + TILE_BYTES)
#define OFF_SLO   (OFF_SHI + TILE_BYTES)
#define OFF_BHI   (OFF_SLO + TILE_BYTES)   // W1-half staging / xw hi
#define OFF_BLO   (OFF_BHI + TILE_BYTES)
#define OFF_W2    (OFF_BLO + TILE_BYTES)   // 208896: 256*4 f32
#define OFF_B1    (OFF_W2 + 4096)
#define OFF_Z     (OFF_B1 + 1024)          // 128*4 f32
#define OFF_ZP    (OFF_Z + 2048)           // 4*128*4 f32
#define OFF_FLAT  (OFF_ZP + 8192)          // 480 f32
#define OFF_RP    (OFF_FLAT + 1920)        // 512 f32
#define OFF_R     (OFF_RP + 2048)          // 64 f32
#define OFF_RED   (OFF_R + 256)            // 16 f32
#define SMEM_BYTES (OFF_RED + 64)          // 228544

// pre-split W1^ tile images: [half][128 rows k=f][PITCH cols n=h'] bf16
__device__ unsigned char g_w1_hi[2 * TILE_BYTES];
__device__ unsigned char g_w1_lo[2 * TILE_BYTES];

__device__ __forceinline__ uint32_t smem_u32(const void* p) {
    uint32_t a;
    asm("{ .reg .u64 t; cvta.to.shared.u64 t, %1; cvt.u32.u64 %0, t; }" : "=r"(a) : "l"(p));
    return a;
}

__device__ __forceinline__ void split2(float a, float b, uint32_t& hw, uint32_t& lw) {
    __nv_bfloat16 ha = __float2bfloat16_rn(a);
    __nv_bfloat16 hb = __float2bfloat16_rn(b);
    __nv_bfloat16 la = __float2bfloat16_rn(a - __bfloat162float(ha));
    __nv_bfloat16 lb = __float2bfloat16_rn(b - __bfloat162float(hb));
    hw = (uint32_t)__bfloat16_as_ushort(ha) | ((uint32_t)__bfloat16_as_ushort(hb) << 16);
    lw = (uint32_t)__bfloat16_as_ushort(la) | ((uint32_t)__bfloat16_as_ushort(lb) << 16);
}
__device__ __forceinline__ float bf_lo(uint32_t w) {
    return __bfloat162float(__ushort_as_bfloat16((unsigned short)(w & 0xffff)));
}
__device__ __forceinline__ float bf_hi(uint32_t w) {
    return __bfloat162float(__ushort_as_bfloat16((unsigned short)(w >> 16)));
}

#define LDSM_X4(r0, r1, r2, r3, addr) \
    asm volatile("ldmatrix.sync.aligned.m8n8.x4.shared.b16 {%0,%1,%2,%3}, [%4];" \
        : "=r"(r0), "=r"(r1), "=r"(r2), "=r"(r3) : "r"(addr))
#define LDSM_X4T(r0, r1, r2, r3, addr) \
    asm volatile("ldmatrix.sync.aligned.m8n8.x4.trans.shared.b16 {%0,%1,%2,%3}, [%4];" \
        : "=r"(r0), "=r"(r1), "=r"(r2), "=r"(r3) : "r"(addr))

__device__ __forceinline__ void mma16816(float* d, uint32_t a0, uint32_t a1,
                                         uint32_t a2, uint32_t a3,
                                         uint32_t b0, uint32_t b1) {
    asm volatile(
        "mma.sync.aligned.m16n8k16.row.col.f32.bf16.bf16.f32 "
        "{%0,%1,%2,%3}, {%4,%5,%6,%7}, {%8,%9}, {%0,%1,%2,%3};"
        : "+f"(d[0]), "+f"(d[1]), "+f"(d[2]), "+f"(d[3])
        : "r"(a0), "r"(a1), "r"(a2), "r"(a3), "r"(b0), "r"(b1));
}

// One product pass: acc[i(2)][j(4)][4] += A(128x128 @ aBase) * B(128x128 @ bBase)
// Warp computes rows [r0, r0+32), cols [c0, c0+32).
__device__ __forceinline__ void mma_pass(float acc[2][4][4],
                                         uint32_t aBase, uint32_t bBase,
                                         int r0, int c0, int lane) {
    const int row_in = (lane & 7) | (((lane >> 3) & 1) << 3);
    const int col_in = (lane >> 4) << 3;
    uint32_t aA0 = aBase + (uint32_t)(((r0 + row_in) * PITCH + col_in) * 2);
    uint32_t aA1 = aA0 + 16 * PITCH * 2;
    uint32_t bB0 = bBase + (uint32_t)((row_in * PITCH + c0 + col_in) * 2);
    uint32_t bB1 = bB0 + 16 * 2;
    #pragma unroll
    for (int k = 0; k < 8; ++k) {
        uint32_t a00, a01, a02, a03, a10, a11, a12, a13;
        uint32_t p0, p1, p2, p3, q0, q1, q2, q3;
        LDSM_X4(a00, a01, a02, a03, aA0);
        LDSM_X4(a10, a11, a12, a13, aA1);
        LDSM_X4T(p0, p1, p2, p3, bB0);
        LDSM_X4T(q0, q1, q2, q3, bB1);
        mma16816(acc[0][0], a00, a01, a02, a03, p0, p1);
        mma16816(acc[0][1], a00, a01, a02, a03, p2, p3);
        mma16816(acc[0][2], a00, a01, a02, a03, q0, q1);
        mma16816(acc[0][3], a00, a01, a02, a03, q2, q3);
        mma16816(acc[1][0], a10, a11, a12, a13, p0, p1);
        mma16816(acc[1][1], a10, a11, a12, a13, p2, p3);
        mma16816(acc[1][2], a10, a11, a12, a13, q0, q1);
        mma16816(acc[1][3], a10, a11, a12, a13, q2, q3);
        aA0 += 32; aA1 += 32;                 // advance 16 cols
        bB0 += 16 * PITCH * 2; bB1 += 16 * PITCH * 2;   // advance 16 rows
    }
}

// ---- prep: split W1 into padded global bf16 tile images (idempotent) ----
__global__ void prep_w1(const float* __restrict__ W1) {
    int idx = blockIdx.x * blockDim.x + threadIdx.x;
    if (idx >= 2 * 128 * PITCH) return;
    int half = idx / (128 * PITCH);
    int rem  = idx % (128 * PITCH);
    int r = rem / PITCH, c = rem % PITCH;     // r = f (K), c = h' (N)
    float v = (r < FIN && c < 128) ? W1[r * HIDD + half * 128 + c] : 0.f;
    __nv_bfloat16 h = __float2bfloat16_rn(v);
    __nv_bfloat16 l = __float2bfloat16_rn(v - __bfloat162float(h));
    *(__nv_bfloat16*)(g_w1_hi + half * TILE_BYTES + (size_t)rem * 2) = h;
    *(__nv_bfloat16*)(g_w1_lo + half * TILE_BYTES + (size_t)rem * 2) = l;
}

extern __shared__ char smc[];

__global__ void __launch_bounds__(512, 1) gcn_mma(
    const float* __restrict__ x,   const float* __restrict__ sup,
    const float* __restrict__ W1,  const float* __restrict__ b1,
    const float* __restrict__ W2,  const float* __restrict__ b2,
    const float* __restrict__ Wr1, const float* __restrict__ br1,
    const float* __restrict__ Wr2, const float* __restrict__ br2,
    float* __restrict__ out)
{
    const int tid  = threadIdx.x;
    const int b    = blockIdx.x;
    const int lane = tid & 31;
    const int warp = tid >> 5;             // 0..15
    const int wr   = warp >> 2;            // row block (0..3) -> rows wr*32
    const int wc   = warp & 3;             // col block (0..3) -> cols wc*32
    const int r0   = wr * 32, c0 = wc * 32;

    float* s_w2   = (float*)(smc + OFF_W2);
    float* s_b1   = (float*)(smc + OFF_B1);
    float* s_z    = (float*)(smc + OFF_Z);
    float* s_zp   = (float*)(smc + OFF_ZP);
    float* s_flat = (float*)(smc + OFF_FLAT);
    float* s_rp   = (float*)(smc + OFF_RP);
    float* s_r    = (float*)(smc + OFF_R);
    float* s_red  = (float*)(smc + OFF_RED);

    const uint32_t su = smem_u32(smc);

    // zero x/sup tiles (pads must be 0) + preload small weights
    for (int i = tid; i < (4 * TILE_BYTES) / 16; i += 512)
        ((uint4*)(smc + OFF_XHI))[i] = make_uint4(0, 0, 0, 0);
    for (int i = tid; i < HIDD * 4; i += 512) s_w2[i] = W2[i];
    for (int i = tid; i < HIDD; i += 512)     s_b1[i] = b1[i];
    __syncthreads();

    // load + split x[b], sup[b] into bf16 hi/lo tiles [m][k], pitch 136
    const float* xb = x   + (size_t)b * NN * FIN;
    const float* sb = sup + (size_t)b * NN * NN;
    for (int q = tid; q < NN * 29; q += 512) {
        int m = q / 29, c4 = (q % 29) * 4;
        uint32_t off = (uint32_t)((m * PITCH + c4) * 2);
        float4 vx = *(const float4*)(xb + m * FIN + c4);
        uint2 hw, lw;
        split2(vx.x, vx.y, hw.x, lw.x);
        split2(vx.z, vx.w, hw.y, lw.y);
        *(uint2*)(smc + OFF_XHI + off) = hw;
        *(uint2*)(smc + OFF_XLO + off) = lw;
        float4 vs = *(const float4*)(sb + m * NN + c4);
        split2(vs.x, vs.y, hw.x, lw.x);
        split2(vs.z, vs.w, hw.y, lw.y);
        *(uint2*)(smc + OFF_SHI + off) = hw;
        *(uint2*)(smc + OFF_SLO + off) = lw;
    }

    float zacc[4][4];
    #pragma unroll
    for (int s = 0; s < 4; s++)
        #pragma unroll
        for (int o = 0; o < 4; o++) zacc[s][o] = 0.f;

    for (int half = 0; half < 2; ++half) {
        // stage W1 half tiles (hi/lo) into BHI/BLO
        {
            const uint4* gh = (const uint4*)(g_w1_hi + half * TILE_BYTES);
            const uint4* gl = (const uint4*)(g_w1_lo + half * TILE_BYTES);
            uint4* bh = (uint4*)(smc + OFF_BHI);
            uint4* bl = (uint4*)(smc + OFF_BLO);
            for (int i = tid; i < TILE_BYTES / 16; i += 512) {
                bh[i] = gh[i];
                bl[i] = gl[i];
            }
        }
        __syncthreads();

        // ---- GEMM1: xw = x @ W1half (3-product) ----
        float acc[2][4][4];
        #pragma unroll
        for (int i = 0; i < 2; i++)
            #pragma unroll
            for (int j = 0; j < 4; j++)
                #pragma unroll
                for (int d = 0; d < 4; d++) acc[i][j][d] = 0.f;

        mma_pass(acc, su + OFF_XHI, su + OFF_BHI, r0, c0, lane);
        mma_pass(acc, su + OFF_XHI, su + OFF_BLO, r0, c0, lane);
        mma_pass(acc, su + OFF_XLO, su + OFF_BHI, r0, c0, lane);
        __syncthreads();   // all W1 tile reads done before overwrite

        // store xw -> BHI/BLO bf16 hi/lo ([m][h'] layout = B of GEMM2)
        {
            int grow = lane >> 2, gcol = (lane & 3) * 2;
            #pragma unroll
            for (int i = 0; i < 2; i++) {
                #pragma unroll
                for (int j = 0; j < 4; j++) {
                    int rr = r0 + i * 16 + grow;
                    int cc = c0 + j * 8 + gcol;
                    uint32_t hw, lw;
                    split2(acc[i][j][0], acc[i][j][1], hw, lw);
                    uint32_t off = (uint32_t)((rr * PITCH + cc) * 2);
                    *(uint32_t*)(smc + OFF_BHI + off) = hw;
                    *(uint32_t*)(smc + OFF_BLO + off) = lw;
                    split2(acc[i][j][2], acc[i][j][3], hw, lw);
                    off = (uint32_t)(((rr + 8) * PITCH + cc) * 2);
                    *(uint32_t*)(smc + OFF_BHI + off) = hw;
                    *(uint32_t*)(smc + OFF_BLO + off) = lw;
                }
            }
        }
        __syncthreads();

        // ---- GEMM2: h1 = sup @ xw (3-product) ----
        #pragma unroll
        for (int i = 0; i < 2; i++)
            #pragma unroll
            for (int j = 0; j < 4; j++)
                #pragma unroll
                for (int d = 0; d < 4; d++) acc[i][j][d] = 0.f;

        mma_pass(acc, su + OFF_SHI, su + OFF_BHI, r0, c0, lane);
        mma_pass(acc, su + OFF_SHI, su + OFF_BLO, r0, c0, lane);
        mma_pass(acc, su + OFF_SLO, su + OFF_BHI, r0, c0, lane);

        // epilogue: relu(h1 + b1) contracted with W2 -> zacc (registers)
        {
            int gcol = (lane & 3) * 2;
            #pragma unroll
            for (int i = 0; i < 2; i++) {
                #pragma unroll
                for (int j = 0; j < 4; j++) {
                    int h = half * 128 + c0 + j * 8 + gcol;
                    float b1a = s_b1[h], b1b = s_b1[h + 1];
                    float4 wa = *(const float4*)&s_w2[h * 4];
                    float4 wb = *(const float4*)&s_w2[(h + 1) * 4];
                    float v0 = fmaxf(acc[i][j][0] + b1a, 0.f);
                    float v1 = fmaxf(acc[i][j][1] + b1b, 0.f);
                    float v2 = fmaxf(acc[i][j][2] + b1a, 0.f);
                    float v3 = fmaxf(acc[i][j][3] + b1b, 0.f);
                    zacc[i*2+0][0] += v0 * wa.x + v1 * wb.x;
                    zacc[i*2+0][1] += v0 * wa.y + v1 * wb.y;
                    zacc[i*2+0][2] += v0 * wa.z + v1 * wb.z;
                    zacc[i*2+0][3] += v0 * wa.w + v1 * wb.w;
                    zacc[i*2+1][0] += v2 * wa.x + v3 * wb.x;
                    zacc[i*2+1][1] += v2 * wa.y + v3 * wb.y;
                    zacc[i*2+1][2] += v2 * wa.z + v3 * wb.z;
                    zacc[i*2+1][3] += v2 * wa.w + v3 * wb.w;
                }
            }
        }
        __syncthreads();   // xw tile reads done before restaging W1
    }

    // reduce zacc over lanes sharing the same row (lane%4 group), store partials
    {
        #pragma unroll
        for (int s = 0; s < 4; s++) {
            #pragma unroll
            for (int o = 0; o < 4; o++) {
                float v = zacc[s][o];
                v += __shfl_xor_sync(0xffffffffu, v, 1);
                v += __shfl_xor_sync(0xffffffffu, v, 2);
                zacc[s][o] = v;
            }
        }
        if ((lane & 3) == 0) {
            #pragma unroll
            for (int s = 0; s < 4; s++) {
                int rr = r0 + (s >> 1) * 16 + (lane >> 2) + (s & 1) * 8;
                #pragma unroll
                for (int o = 0; o < 4; o++)
                    s_zp[(wc * 128 + rr) * 4 + o] = zacc[s][o];
            }
        }
    }
    __syncthreads();
    {
        int n = tid >> 2, o = tid & 3;
        s_z[n * 4 + o] = s_zp[(0 * 128 + n) * 4 + o] + s_zp[(1 * 128 + n) * 4 + o]
                       + s_zp[(2 * 128 + n) * 4 + o] + s_zp[(3 * 128 + n) * 4 + o];
    }
    __syncthreads();

    // h2 = relu(sup @ z + b2) -> flat[464]   (sup reconstructed hi+lo)
    if (tid < NN * 4) {
        int n = tid >> 2, o = tid & 3;
        float acc2 = 0.f;
        #pragma unroll
        for (int u = 0; u < 15; u++) {
            uint32_t off = (uint32_t)((n * PITCH + u * 8) * 2);
            uint4 uh = *(const uint4*)(smc + OFF_SHI + off);
            uint4 ul = *(const uint4*)(smc + OFF_SLO + off);
            uint32_t hw[4] = {uh.x, uh.y, uh.z, uh.w};
            uint32_t lw[4] = {ul.x, ul.y, ul.z, ul.w};
            #pragma unroll
            for (int p = 0; p < 4; p++) {
                int m0 = u * 8 + p * 2;
                float s0 = bf_lo(hw[p]) + bf_lo(lw[p]);
                float s1 = bf_hi(hw[p]) + bf_hi(lw[p]);
                acc2 += s0 * s_z[m0 * 4 + o] + s1 * s_z[(m0 + 1) * 4 + o];
            }
        }
        s_flat[tid] = fmaxf(acc2 + b2[o], 0.f);
    }
    __syncthreads();

    // r = relu(flat @ Wr1 + br1): 464x64, 8 partials per output
    {
        int j = tid & 63, p = tid >> 6;
        int i0 = p * 58;
        float a0 = 0.f, a1 = 0.f;
        #pragma unroll 2
        for (int i = 0; i < 58; i += 2) {
            a0 += s_flat[i0 + i]     * Wr1[(size_t)(i0 + i)     * 64 + j];
            a1 += s_flat[i0 + i + 1] * Wr1[(size_t)(i0 + i + 1) * 64 + j];
        }
        s_rp[p * 64 + j] = a0 + a1;
    }
    __syncthreads();
    if (tid < 64) {
        float v = br1[tid];
        #pragma unroll
        for (int p = 0; p < 8; p++) v += s_rp[p * 64 + tid];
        s_r[tid] = fmaxf(v, 0.f);
    }
    __syncthreads();

    // logits = r @ Wr2 + br2 ; log_softmax (2 classes)
    if (tid < 64) {
        float rv = s_r[tid];
        float p0 = rv * Wr2[tid * 2 + 0];
        float p1 = rv * Wr2[tid * 2 + 1];
        #pragma unroll
        for (int m = 16; m >= 1; m >>= 1) {
            p0 += __shfl_xor_sync(0xffffffffu, p0, m);
            p1 += __shfl_xor_sync(0xffffffffu, p1, m);
        }
        if ((tid & 31) == 0) {
            s_red[(tid >> 5) * 2 + 0] = p0;
            s_red[(tid >> 5) * 2 + 1] = p1;
        }
    }
    __syncthreads();
    if (tid == 0) {
        float l0 = s_red[0] + s_red[2] + br2[0];
        float l1 = s_red[1] + s_red[3] + br2[1];
        float mx = fmaxf(l0, l1);
        float lse = mx + logf(expf(l0 - mx) + expf(l1 - mx));
        out[(size_t)b * 2 + 0] = l0 - lse;
        out[(size_t)b * 2 + 1] = l1 - lse;
    }
}

extern "C" void kernel_launch(void* const* d_in, const int* in_sizes, int n_in,
                              void* d_out, int out_size) {
    const float* x   = (const float*)d_in[0];
    const float* sup = (const float*)d_in[1];
    const float* W1  = (const float*)d_in[2];
    const float* b1  = (const float*)d_in[3];
    const float* W2  = (const float*)d_in[4];
    const float* b2  = (const float*)d_in[5];
    const float* Wr1 = (const float*)d_in[6];
    const float* br1 = (const float*)d_in[7];
    const float* Wr2 = (const float*)d_in[8];
    const float* br2 = (const float*)d_in[9];
    float* out = (float*)d_out;

    int B = in_sizes[0] / (NN * FIN);

    prep_w1<<<(2 * 128 * PITCH + 255) / 256, 256>>>(W1);

    cudaFuncSetAttribute(gcn_mma, cudaFuncAttributeMaxDynamicSharedMemorySize, SMEM_BYTES);
    gcn_mma<<<B, 512, SMEM_BYTES>>>(x, sup, W1, b1, W2, b2, Wr1, br1, Wr2, br2, out);
}

// round 5
// speedup vs baseline: 2.8587x; 1.6349x over previous
#include <cuda_runtime.h>
#include <cuda_bf16.h>
#include <cstdint>

#define NN   116
#define FIN  116
#define HIDD 256
#define PITCH 136                       // bf16 elems per tile row (272B)
#define TILE_BYTES (128 * PITCH * 2)    // 34816

// ---- SMEM byte offsets ----
#define OFF_XHI   0
#define OFF_XLO   (OFF_XHI + TILE_BYTES)
#define OFF_SHI   (OFF_XLO + TILE_BYTES)
#define OFF_SLO   (OFF_SHI + TILE_BYTES)
#define OFF_W1B   (OFF_SLO + TILE_BYTES)   // W1-half (single bf16)
#define OFF_XW    (OFF_W1B + TILE_BYTES)   // xw (single bf16)
#define OFF_W2    (OFF_XW + TILE_BYTES)    // 256*4 f32
#define OFF_B1    (OFF_W2 + 4096)
#define OFF_Z     (OFF_B1 + 1024)          // 128*4 f32
#define OFF_ZP    (OFF_Z + 2048)           // 4*128*4 f32
#define OFF_FLAT  (OFF_ZP + 8192)          // 480 f32
#define OFF_RP    (OFF_FLAT + 1920)        // 512 f32
#define OFF_R     (OFF_RP + 2048)          // 64 f32
#define OFF_RED   (OFF_R + 256)            // 16 f32
#define SMEM_BYTES (OFF_RED + 64)          // 228544

// pre-rounded W1 tile images: [half][128 rows k=f][PITCH cols n=h'] bf16
__device__ unsigned char g_w1[2 * TILE_BYTES];

__device__ __forceinline__ uint32_t smem_u32(const void* p) {
    uint32_t a;
    asm("{ .reg .u64 t; cvta.to.shared.u64 t, %1; cvt.u32.u64 %0, t; }" : "=r"(a) : "l"(p));
    return a;
}

__device__ __forceinline__ void split2(float a, float b, uint32_t& hw, uint32_t& lw) {
    __nv_bfloat16 ha = __float2bfloat16_rn(a);
    __nv_bfloat16 hb = __float2bfloat16_rn(b);
    __nv_bfloat16 la = __float2bfloat16_rn(a - __bfloat162float(ha));
    __nv_bfloat16 lb = __float2bfloat16_rn(b - __bfloat162float(hb));
    hw = (uint32_t)__bfloat16_as_ushort(ha) | ((uint32_t)__bfloat16_as_ushort(hb) << 16);
    lw = (uint32_t)__bfloat16_as_ushort(la) | ((uint32_t)__bfloat16_as_ushort(lb) << 16);
}
__device__ __forceinline__ uint32_t pack_bf16(float a, float b) {
    __nv_bfloat162 v = __float22bfloat162_rn(make_float2(a, b));
    return *(uint32_t*)&v;
}
__device__ __forceinline__ float bf_lo(uint32_t w) {
    return __bfloat162float(__ushort_as_bfloat16((unsigned short)(w & 0xffff)));
}
__device__ __forceinline__ float bf_hi(uint32_t w) {
    return __bfloat162float(__ushort_as_bfloat16((unsigned short)(w >> 16)));
}

__device__ __forceinline__ void cpasync16(uint32_t s, const void* g) {
    asm volatile("cp.async.cg.shared.global [%0], [%1], 16;" :: "r"(s), "l"(g));
}
#define CP_COMMIT() asm volatile("cp.async.commit_group;")
#define CP_WAIT0()  asm volatile("cp.async.wait_group 0;")

#define LDSM_X4(r0, r1, r2, r3, addr) \
    asm volatile("ldmatrix.sync.aligned.m8n8.x4.shared.b16 {%0,%1,%2,%3}, [%4];" \
        : "=r"(r0), "=r"(r1), "=r"(r2), "=r"(r3) : "r"(addr))
#define LDSM_X4T(r0, r1, r2, r3, addr) \
    asm volatile("ldmatrix.sync.aligned.m8n8.x4.trans.shared.b16 {%0,%1,%2,%3}, [%4];" \
        : "=r"(r0), "=r"(r1), "=r"(r2), "=r"(r3) : "r"(addr))

__device__ __forceinline__ void mma16816(float* d, uint32_t a0, uint32_t a1,
                                         uint32_t a2, uint32_t a3,
                                         uint32_t b0, uint32_t b1) {
    asm volatile(
        "mma.sync.aligned.m16n8k16.row.col.f32.bf16.bf16.f32 "
        "{%0,%1,%2,%3}, {%4,%5,%6,%7}, {%8,%9}, {%0,%1,%2,%3};"
        : "+f"(d[0]), "+f"(d[1]), "+f"(d[2]), "+f"(d[3])
        : "r"(a0), "r"(a1), "r"(a2), "r"(a3), "r"(b0), "r"(b1));
}

// 2-product GEMM: acc += (Ahi + Alo) * B.  Warp tile rows [r0,r0+32), cols [c0,c0+32).
__device__ __forceinline__ void mma_2p(float acc[2][4][4],
                                       uint32_t aHi, uint32_t aLo, uint32_t bB,
                                       int r0, int c0, int lane) {
    const int row_in = (lane & 7) | (((lane >> 3) & 1) << 3);
    const int col_in = (lane >> 4) << 3;
    uint32_t h0a = aHi + (uint32_t)(((r0 + row_in) * PITCH + col_in) * 2);
    uint32_t h1a = h0a + 16 * PITCH * 2;
    uint32_t l0a = aLo + (uint32_t)(((r0 + row_in) * PITCH + col_in) * 2);
    uint32_t l1a = l0a + 16 * PITCH * 2;
    uint32_t b0a = bB + (uint32_t)((row_in * PITCH + c0 + col_in) * 2);
    uint32_t b1a = b0a + 16 * 2;
    #pragma unroll
    for (int k = 0; k < 8; ++k) {
        uint32_t h00, h01, h02, h03, h10, h11, h12, h13;
        uint32_t l00, l01, l02, l03, l10, l11, l12, l13;
        uint32_t p0, p1, p2, p3, q0, q1, q2, q3;
        LDSM_X4(h00, h01, h02, h03, h0a);
        LDSM_X4(h10, h11, h12, h13, h1a);
        LDSM_X4(l00, l01, l02, l03, l0a);
        LDSM_X4(l10, l11, l12, l13, l1a);
        LDSM_X4T(p0, p1, p2, p3, b0a);
        LDSM_X4T(q0, q1, q2, q3, b1a);
        mma16816(acc[0][0], h00, h01, h02, h03, p0, p1);
        mma16816(acc[0][1], h00, h01, h02, h03, p2, p3);
        mma16816(acc[0][2], h00, h01, h02, h03, q0, q1);
        mma16816(acc[0][3], h00, h01, h02, h03, q2, q3);
        mma16816(acc[1][0], h10, h11, h12, h13, p0, p1);
        mma16816(acc[1][1], h10, h11, h12, h13, p2, p3);
        mma16816(acc[1][2], h10, h11, h12, h13, q0, q1);
        mma16816(acc[1][3], h10, h11, h12, h13, q2, q3);
        mma16816(acc[0][0], l00, l01, l02, l03, p0, p1);
        mma16816(acc[0][1], l00, l01, l02, l03, p2, p3);
        mma16816(acc[0][2], l00, l01, l02, l03, q0, q1);
        mma16816(acc[0][3], l00, l01, l02, l03, q2, q3);
        mma16816(acc[1][0], l10, l11, l12, l13, p0, p1);
        mma16816(acc[1][1], l10, l11, l12, l13, p2, p3);
        mma16816(acc[1][2], l10, l11, l12, l13, q0, q1);
        mma16816(acc[1][3], l10, l11, l12, l13, q2, q3);
        h0a += 32; h1a += 32; l0a += 32; l1a += 32;       // +16 cols
        b0a += 16 * PITCH * 2; b1a += 16 * PITCH * 2;     // +16 rows
    }
}

// ---- prep: round W1 into padded global bf16 tile images (idempotent) ----
__global__ void prep_w1(const float* __restrict__ W1) {
    int idx = blockIdx.x * blockDim.x + threadIdx.x;
    if (idx >= 2 * 128 * PITCH) return;
    int half = idx / (128 * PITCH);
    int rem  = idx % (128 * PITCH);
    int r = rem / PITCH, c = rem % PITCH;     // r = f (K), c = h' (N)
    float v = (r < FIN && c < 128) ? W1[r * HIDD + half * 128 + c] : 0.f;
    *(__nv_bfloat16*)(g_w1 + half * TILE_BYTES + (size_t)rem * 2) = __float2bfloat16_rn(v);
}

extern __shared__ char smc[];

__global__ void __launch_bounds__(512, 1) gcn_mma(
    const float* __restrict__ x,   const float* __restrict__ sup,
    const float* __restrict__ W1,  const float* __restrict__ b1,
    const float* __restrict__ W2,  const float* __restrict__ b2,
    const float* __restrict__ Wr1, const float* __restrict__ br1,
    const float* __restrict__ Wr2, const float* __restrict__ br2,
    float* __restrict__ out)
{
    const int tid  = threadIdx.x;
    const int b    = blockIdx.x;
    const int lane = tid & 31;
    const int warp = tid >> 5;             // 0..15
    const int wr   = warp >> 2;
    const int wc   = warp & 3;
    const int r0   = wr * 32, c0 = wc * 32;

    float* s_w2   = (float*)(smc + OFF_W2);
    float* s_b1   = (float*)(smc + OFF_B1);
    float* s_z    = (float*)(smc + OFF_Z);
    float* s_zp   = (float*)(smc + OFF_ZP);
    float* s_flat = (float*)(smc + OFF_FLAT);
    float* s_rp   = (float*)(smc + OFF_RP);
    float* s_r    = (float*)(smc + OFF_R);
    float* s_red  = (float*)(smc + OFF_RED);

    const uint32_t su = smem_u32(smc);

    // prefetch W1 half0 via cp.async (overlaps with conversion below)
    for (int i = tid; i < TILE_BYTES / 16; i += 512)
        cpasync16(su + OFF_W1B + i * 16, g_w1 + i * 16);
    CP_COMMIT();

    // zero x/sup tiles (pads must be 0) + preload small weights
    for (int i = tid; i < (4 * TILE_BYTES) / 16; i += 512)
        ((uint4*)(smc + OFF_XHI))[i] = make_uint4(0, 0, 0, 0);
    for (int i = tid; i < HIDD * 4; i += 512) s_w2[i] = W2[i];
    for (int i = tid; i < HIDD; i += 512)     s_b1[i] = b1[i];
    __syncthreads();

    // load + split x[b], sup[b] into bf16 hi/lo tiles [m][k], pitch 136
    const float* xb = x   + (size_t)b * NN * FIN;
    const float* sb = sup + (size_t)b * NN * NN;
    for (int q = tid; q < NN * 29; q += 512) {
        int m = q / 29, c4 = (q % 29) * 4;
        uint32_t off = (uint32_t)((m * PITCH + c4) * 2);
        float4 vx = *(const float4*)(xb + m * FIN + c4);
        uint2 hw, lw;
        split2(vx.x, vx.y, hw.x, lw.x);
        split2(vx.z, vx.w, hw.y, lw.y);
        *(uint2*)(smc + OFF_XHI + off) = hw;
        *(uint2*)(smc + OFF_XLO + off) = lw;
        float4 vs = *(const float4*)(sb + m * NN + c4);
        split2(vs.x, vs.y, hw.x, lw.x);
        split2(vs.z, vs.w, hw.y, lw.y);
        *(uint2*)(smc + OFF_SHI + off) = hw;
        *(uint2*)(smc + OFF_SLO + off) = lw;
    }
    CP_WAIT0();
    __syncthreads();

    float zacc[4][4];
    #pragma unroll
    for (int s = 0; s < 4; s++)
        #pragma unroll
        for (int o = 0; o < 4; o++) zacc[s][o] = 0.f;

    for (int half = 0; half < 2; ++half) {
        // ---- GEMM1: xw = x @ W1half (A = x hi/lo, B = W1 bf16) ----
        float acc[2][4][4];
        #pragma unroll
        for (int i = 0; i < 2; i++)
            #pragma unroll
            for (int j = 0; j < 4; j++)
                #pragma unroll
                for (int d = 0; d < 4; d++) acc[i][j][d] = 0.f;

        mma_2p(acc, su + OFF_XHI, su + OFF_XLO, su + OFF_W1B, r0, c0, lane);
        __syncthreads();   // all W1 reads done

        // prefetch W1 half1 while GEMM2(half0) runs
        if (half == 0) {
            for (int i = tid; i < TILE_BYTES / 16; i += 512)
                cpasync16(su + OFF_W1B + i * 16, g_w1 + TILE_BYTES + i * 16);
            CP_COMMIT();
        }

        // store xw as single bf16 ([m][h'] layout = B of GEMM2)
        {
            int grow = lane >> 2, gcol = (lane & 3) * 2;
            #pragma unroll
            for (int i = 0; i < 2; i++) {
                #pragma unroll
                for (int j = 0; j < 4; j++) {
                    int rr = r0 + i * 16 + grow;
                    int cc = c0 + j * 8 + gcol;
                    *(uint32_t*)(smc + OFF_XW + (uint32_t)((rr * PITCH + cc) * 2)) =
                        pack_bf16(acc[i][j][0], acc[i][j][1]);
                    *(uint32_t*)(smc + OFF_XW + (uint32_t)(((rr + 8) * PITCH + cc) * 2)) =
                        pack_bf16(acc[i][j][2], acc[i][j][3]);
                }
            }
        }
        __syncthreads();

        // ---- GEMM2: h1 = sup @ xw (A = sup hi/lo, B = xw bf16) ----
        #pragma unroll
        for (int i = 0; i < 2; i++)
            #pragma unroll
            for (int j = 0; j < 4; j++)
                #pragma unroll
                for (int d = 0; d < 4; d++) acc[i][j][d] = 0.f;

        mma_2p(acc, su + OFF_SHI, su + OFF_SLO, su + OFF_XW, r0, c0, lane);

        // epilogue: relu(h1 + b1) contracted with W2 -> zacc (registers)
        {
            int gcol = (lane & 3) * 2;
            #pragma unroll
            for (int i = 0; i < 2; i++) {
                #pragma unroll
                for (int j = 0; j < 4; j++) {
                    int h = half * 128 + c0 + j * 8 + gcol;
                    float b1a = s_b1[h], b1b = s_b1[h + 1];
                    float4 wa = *(const float4*)&s_w2[h * 4];
                    float4 wb = *(const float4*)&s_w2[(h + 1) * 4];
                    float v0 = fmaxf(acc[i][j][0] + b1a, 0.f);
                    float v1 = fmaxf(acc[i][j][1] + b1b, 0.f);
                    float v2 = fmaxf(acc[i][j][2] + b1a, 0.f);
                    float v3 = fmaxf(acc[i][j][3] + b1b, 0.f);
                    zacc[i*2+0][0] += v0 * wa.x + v1 * wb.x;
                    zacc[i*2+0][1] += v0 * wa.y + v1 * wb.y;
                    zacc[i*2+0][2] += v0 * wa.z + v1 * wb.z;
                    zacc[i*2+0][3] += v0 * wa.w + v1 * wb.w;
                    zacc[i*2+1][0] += v2 * wa.x + v3 * wb.x;
                    zacc[i*2+1][1] += v2 * wa.y + v3 * wb.y;
                    zacc[i*2+1][2] += v2 * wa.z + v3 * wb.z;
                    zacc[i*2+1][3] += v2 * wa.w + v3 * wb.w;
                }
            }
        }
        if (half == 0) { CP_WAIT0(); }
        __syncthreads();   // xw reads done; W1 half1 landed
    }

    // reduce zacc over lanes sharing the same row (lane%4 group), store partials
    {
        #pragma unroll
        for (int s = 0; s < 4; s++) {
            #pragma unroll
            for (int o = 0; o < 4; o++) {
                float v = zacc[s][o];
                v += __shfl_xor_sync(0xffffffffu, v, 1);
                v += __shfl_xor_sync(0xffffffffu, v, 2);
                zacc[s][o] = v;
            }
        }
        if ((lane & 3) == 0) {
            #pragma unroll
            for (int s = 0; s < 4; s++) {
                int rr = r0 + (s >> 1) * 16 + (lane >> 2) + (s & 1) * 8;
                #pragma unroll
                for (int o = 0; o < 4; o++)
                    s_zp[(wc * 128 + rr) * 4 + o] = zacc[s][o];
            }
        }
    }
    __syncthreads();
    {
        int n = tid >> 2, o = tid & 3;
        s_z[n * 4 + o] = s_zp[(0 * 128 + n) * 4 + o] + s_zp[(1 * 128 + n) * 4 + o]
                       + s_zp[(2 * 128 + n) * 4 + o] + s_zp[(3 * 128 + n) * 4 + o];
    }
    __syncthreads();

    // h2 = relu(sup @ z + b2) -> flat[464]   (sup reconstructed hi+lo)
    if (tid < NN * 4) {
        int n = tid >> 2, o = tid & 3;
        float acc2 = 0.f;
        #pragma unroll
        for (int u = 0; u < 15; u++) {
            uint32_t off = (uint32_t)((n * PITCH + u * 8) * 2);
            uint4 uh = *(const uint4*)(smc + OFF_SHI + off);
            uint4 ul = *(const uint4*)(smc + OFF_SLO + off);
            uint32_t hw[4] = {uh.x, uh.y, uh.z, uh.w};
            uint32_t lw[4] = {ul.x, ul.y, ul.z, ul.w};
            #pragma unroll
            for (int p = 0; p < 4; p++) {
                int m0 = u * 8 + p * 2;
                float s0 = bf_lo(hw[p]) + bf_lo(lw[p]);
                float s1 = bf_hi(hw[p]) + bf_hi(lw[p]);
                acc2 += s0 * s_z[m0 * 4 + o] + s1 * s_z[(m0 + 1) * 4 + o];
            }
        }
        s_flat[tid] = fmaxf(acc2 + b2[o], 0.f);
    }
    __syncthreads();

    // r = relu(flat @ Wr1 + br1): 464x64, 8 partials per output
    {
        int j = tid & 63, p = tid >> 6;
        int i0 = p * 58;
        float a0 = 0.f, a1 = 0.f;
        #pragma unroll 2
        for (int i = 0; i < 58; i += 2) {
            a0 += s_flat[i0 + i]     * Wr1[(size_t)(i0 + i)     * 64 + j];
            a1 += s_flat[i0 + i + 1] * Wr1[(size_t)(i0 + i + 1) * 64 + j];
        }
        s_rp[p * 64 + j] = a0 + a1;
    }
    __syncthreads();
    if (tid < 64) {
        float v = br1[tid];
        #pragma unroll
        for (int p = 0; p < 8; p++) v += s_rp[p * 64 + tid];
        s_r[tid] = fmaxf(v, 0.f);
    }
    __syncthreads();

    // logits = r @ Wr2 + br2 ; log_softmax (2 classes)
    if (tid < 64) {
        float rv = s_r[tid];
        float p0 = rv * Wr2[tid * 2 + 0];
        float p1 = rv * Wr2[tid * 2 + 1];
        #pragma unroll
        for (int m = 16; m >= 1; m >>= 1) {
            p0 += __shfl_xor_sync(0xffffffffu, p0, m);
            p1 += __shfl_xor_sync(0xffffffffu, p1, m);
        }
        if ((tid & 31) == 0) {
            s_red[(tid >> 5) * 2 + 0] = p0;
            s_red[(tid >> 5) * 2 + 1] = p1;
        }
    }
    __syncthreads();
    if (tid == 0) {
        float l0 = s_red[0] + s_red[2] + br2[0];
        float l1 = s_red[1] + s_red[3] + br2[1];
        float mx = fmaxf(l0, l1);
        float lse = mx + logf(expf(l0 - mx) + expf(l1 - mx));
        out[(size_t)b * 2 + 0] = l0 - lse;
        out[(size_t)b * 2 + 1] = l1 - lse;
    }
}

extern "C" void kernel_launch(void* const* d_in, const int* in_sizes, int n_in,
                              void* d_out, int out_size) {
    const float* x   = (const float*)d_in[0];
    const float* sup = (const float*)d_in[1];
    const float* W1  = (const float*)d_in[2];
    const float* b1  = (const float*)d_in[3];
    const float* W2  = (const float*)d_in[4];
    const float* b2  = (const float*)d_in[5];
    const float* Wr1 = (const float*)d_in[6];
    const float* br1 = (const float*)d_in[7];
    const float* Wr2 = (const float*)d_in[8];
    const float* br2 = (const float*)d_in[9];
    float* out = (float*)d_out;

    int B = in_sizes[0] / (NN * FIN);

    prep_w1<<<(2 * 128 * PITCH + 255) / 256, 256>>>(W1);

    cudaFuncSetAttribute(gcn_mma, cudaFuncAttributeMaxDynamicSharedMemorySize, SMEM_BYTES);
    gcn_mma<<<B, 512, SMEM_BYTES>>>(x, sup, W1, b1, W2, b2, Wr1, br1, Wr2, br2, out);
}

// round 6
// speedup vs baseline: 3.9574x; 1.3843x over previous
#include <cuda_runtime.h>
#include <cuda_bf16.h>
#include <cstdint>

#define NN   116
#define FIN  116
#define HIDD 256
#define PITCH 136                       // bf16 elems per tile row (272B)
#define TILE_BYTES (128 * PITCH * 2)    // 34816

// ---- SMEM byte offsets ----
#define OFF_X     0
#define OFF_SUP   (OFF_X   + TILE_BYTES)
#define OFF_B0    (OFF_SUP + TILE_BYTES)   // W1 half0 -> xw half0
#define OFF_B1T   (OFF_B0  + TILE_BYTES)   // W1 half1 -> xw half1
#define OFF_W2    (OFF_B1T + TILE_BYTES)   // 256*4 f32
#define OFF_B1V   (OFF_W2  + 4096)         // 256 f32
#define OFF_Z     (OFF_B1V + 1024)         // 128*4 f32
#define OFF_ZP    (OFF_Z   + 2048)         // 4*128*4 f32
#define OFF_FLAT  (OFF_ZP  + 8192)         // 480 f32
#define OFF_RP    (OFF_FLAT + 1920)        // 512 f32
#define OFF_R     (OFF_RP  + 2048)         // 64 f32
#define OFF_RED   (OFF_R   + 256)          // 16 f32
#define SMEM_BYTES (OFF_RED + 64)          // 158912

// pre-rounded W1 tile images: [half][128 rows k=f][PITCH cols n=h'] bf16
__device__ unsigned char g_w1[2 * TILE_BYTES];

__device__ __forceinline__ uint32_t smem_u32(const void* p) {
    uint32_t a;
    asm("{ .reg .u64 t; cvta.to.shared.u64 t, %1; cvt.u32.u64 %0, t; }" : "=r"(a) : "l"(p));
    return a;
}
__device__ __forceinline__ uint32_t pack_bf16(float a, float b) {
    __nv_bfloat162 v = __float22bfloat162_rn(make_float2(a, b));
    return *(uint32_t*)&v;
}
__device__ __forceinline__ float bf_lo(uint32_t w) {
    return __bfloat162float(__ushort_as_bfloat16((unsigned short)(w & 0xffff)));
}
__device__ __forceinline__ float bf_hi(uint32_t w) {
    return __bfloat162float(__ushort_as_bfloat16((unsigned short)(w >> 16)));
}

__device__ __forceinline__ void cpasync16(uint32_t s, const void* g) {
    asm volatile("cp.async.cg.shared.global [%0], [%1], 16;" :: "r"(s), "l"(g));
}
#define CP_COMMIT() asm volatile("cp.async.commit_group;")
#define CP_WAIT0()  asm volatile("cp.async.wait_group 0;")

#define LDSM_X4(r0, r1, r2, r3, addr) \
    asm volatile("ldmatrix.sync.aligned.m8n8.x4.shared.b16 {%0,%1,%2,%3}, [%4];" \
        : "=r"(r0), "=r"(r1), "=r"(r2), "=r"(r3) : "r"(addr))
#define LDSM_X4T(r0, r1, r2, r3, addr) \
    asm volatile("ldmatrix.sync.aligned.m8n8.x4.trans.shared.b16 {%0,%1,%2,%3}, [%4];" \
        : "=r"(r0), "=r"(r1), "=r"(r2), "=r"(r3) : "r"(addr))

__device__ __forceinline__ void mma16816(float* d, uint32_t a0, uint32_t a1,
                                         uint32_t a2, uint32_t a3,
                                         uint32_t b0, uint32_t b1) {
    asm volatile(
        "mma.sync.aligned.m16n8k16.row.col.f32.bf16.bf16.f32 "
        "{%0,%1,%2,%3}, {%4,%5,%6,%7}, {%8,%9}, {%0,%1,%2,%3};"
        : "+f"(d[0]), "+f"(d[1]), "+f"(d[2]), "+f"(d[3])
        : "r"(a0), "r"(a1), "r"(a2), "r"(a3), "r"(b0), "r"(b1));
}

// 1-product GEMM: acc[2][8][4] += A * B.  Warp tile: rows [r0,r0+32), cols [c0,c0+64).
__device__ __forceinline__ void mma_1p(float acc[2][8][4],
                                       uint32_t aBase, uint32_t bBase,
                                       int r0, int c0, int lane) {
    const int row_in = (lane & 7) | (((lane >> 3) & 1) << 3);
    const int col_in = (lane >> 4) << 3;
    uint32_t aA = aBase + (uint32_t)(((r0 + row_in) * PITCH + col_in) * 2);
    uint32_t bB = bBase + (uint32_t)((row_in * PITCH + c0 + col_in) * 2);
    #pragma unroll
    for (int k = 0; k < 8; ++k) {
        uint32_t a0, a1, a2, a3, a4, a5, a6, a7;
        LDSM_X4(a0, a1, a2, a3, aA);
        LDSM_X4(a4, a5, a6, a7, aA + 16 * PITCH * 2);
        #pragma unroll
        for (int jj = 0; jj < 2; ++jj) {
            uint32_t p0, p1, p2, p3, q0, q1, q2, q3;
            LDSM_X4T(p0, p1, p2, p3, bB + jj * 64);
            LDSM_X4T(q0, q1, q2, q3, bB + jj * 64 + 32);
            mma16816(acc[0][jj * 4 + 0], a0, a1, a2, a3, p0, p1);
            mma16816(acc[0][jj * 4 + 1], a0, a1, a2, a3, p2, p3);
            mma16816(acc[0][jj * 4 + 2], a0, a1, a2, a3, q0, q1);
            mma16816(acc[0][jj * 4 + 3], a0, a1, a2, a3, q2, q3);
            mma16816(acc[1][jj * 4 + 0], a4, a5, a6, a7, p0, p1);
            mma16816(acc[1][jj * 4 + 1], a4, a5, a6, a7, p2, p3);
            mma16816(acc[1][jj * 4 + 2], a4, a5, a6, a7, q0, q1);
            mma16816(acc[1][jj * 4 + 3], a4, a5, a6, a7, q2, q3);
        }
        aA += 32;                  // +16 k-cols
        bB += 16 * PITCH * 2;      // +16 k-rows
    }
}

// ---- prep: round W1 into padded global bf16 tile images (idempotent) ----
__global__ void prep_w1(const float* __restrict__ W1) {
    int idx = blockIdx.x * blockDim.x + threadIdx.x;
    if (idx >= 2 * 128 * PITCH) return;
    int half = idx / (128 * PITCH);
    int rem  = idx % (128 * PITCH);
    int r = rem / PITCH, c = rem % PITCH;     // r = f (K), c = h' (N)
    float v = (r < FIN && c < 128) ? W1[r * HIDD + half * 128 + c] : 0.f;
    *(__nv_bfloat16*)(g_w1 + half * TILE_BYTES + (size_t)rem * 2) = __float2bfloat16_rn(v);
}

extern __shared__ char smc[];

__global__ void __launch_bounds__(512, 1) gcn_mma(
    const float* __restrict__ x,   const float* __restrict__ sup,
    const float* __restrict__ W1,  const float* __restrict__ b1,
    const float* __restrict__ W2,  const float* __restrict__ b2,
    const float* __restrict__ Wr1, const float* __restrict__ br1,
    const float* __restrict__ Wr2, const float* __restrict__ br2,
    float* __restrict__ out)
{
    const int tid  = threadIdx.x;
    const int b    = blockIdx.x;
    const int lane = tid & 31;
    const int warp = tid >> 5;            // 0..15
    const int half = warp >> 3;           // 0,1: which HID half this warp works on
    const int w8   = warp & 7;
    const int r0   = (w8 >> 1) * 32;      // 4 row blocks
    const int c0   = (w8 & 1) * 64;       // 2 col blocks of 64

    float* s_w2   = (float*)(smc + OFF_W2);
    float* s_b1   = (float*)(smc + OFF_B1V);
    float* s_z    = (float*)(smc + OFF_Z);
    float* s_zp   = (float*)(smc + OFF_ZP);
    float* s_flat = (float*)(smc + OFF_FLAT);
    float* s_rp   = (float*)(smc + OFF_RP);
    float* s_r    = (float*)(smc + OFF_R);
    float* s_red  = (float*)(smc + OFF_RED);

    const uint32_t su = smem_u32(smc);
    const uint32_t bufBase = su + (half ? OFF_B1T : OFF_B0);

    // prefetch W1 (both halves) via cp.async — overlaps everything below
    for (int i = tid; i < (2 * TILE_BYTES) / 16; i += 512)
        cpasync16(su + OFF_B0 + i * 16, g_w1 + i * 16);
    CP_COMMIT();

    // zero x/sup tiles (pads must be 0) + preload small weights
    for (int i = tid; i < (2 * TILE_BYTES) / 16; i += 512)
        ((uint4*)(smc + OFF_X))[i] = make_uint4(0, 0, 0, 0);
    for (int i = tid; i < HIDD * 4; i += 512) s_w2[i] = W2[i];
    for (int i = tid; i < HIDD; i += 512)     s_b1[i] = b1[i];
    __syncthreads();

    // load + convert x[b], sup[b] -> single bf16 tiles [m][k], pitch 136
    const float* xb = x   + (size_t)b * NN * FIN;
    const float* sb = sup + (size_t)b * NN * NN;
    for (int q = tid; q < NN * 29; q += 512) {
        int m = q / 29, c4 = (q % 29) * 4;
        uint32_t off = (uint32_t)((m * PITCH + c4) * 2);
        float4 vx = *(const float4*)(xb + m * FIN + c4);
        uint2 w;
        w.x = pack_bf16(vx.x, vx.y);
        w.y = pack_bf16(vx.z, vx.w);
        *(uint2*)(smc + OFF_X + off) = w;
        float4 vs = *(const float4*)(sb + m * NN + c4);
        w.x = pack_bf16(vs.x, vs.y);
        w.y = pack_bf16(vs.z, vs.w);
        *(uint2*)(smc + OFF_SUP + off) = w;
    }
    CP_WAIT0();
    __syncthreads();

    // ---- GEMM1 (both halves concurrently): xw = x @ W1half ----
    float acc[2][8][4];
    #pragma unroll
    for (int i = 0; i < 2; i++)
        #pragma unroll
        for (int j = 0; j < 8; j++)
            #pragma unroll
            for (int d = 0; d < 4; d++) acc[i][j][d] = 0.f;

    mma_1p(acc, su + OFF_X, bufBase, r0, c0, lane);
    __syncthreads();   // all W1 reads done before overwrite

    // store xw as bf16 into the same buffer ([m][h'] layout = B of GEMM2)
    {
        int grow = lane >> 2, gcol = (lane & 3) * 2;
        #pragma unroll
        for (int i = 0; i < 2; i++) {
            #pragma unroll
            for (int j = 0; j < 8; j++) {
                int rr = r0 + i * 16 + grow;
                int cc = c0 + j * 8 + gcol;
                *(uint32_t*)(smc + (bufBase - su) + (uint32_t)((rr * PITCH + cc) * 2)) =
                    pack_bf16(acc[i][j][0], acc[i][j][1]);
                *(uint32_t*)(smc + (bufBase - su) + (uint32_t)(((rr + 8) * PITCH + cc) * 2)) =
                    pack_bf16(acc[i][j][2], acc[i][j][3]);
            }
        }
    }
    __syncthreads();

    // ---- GEMM2 (both halves concurrently): h1 = sup @ xw ----
    #pragma unroll
    for (int i = 0; i < 2; i++)
        #pragma unroll
        for (int j = 0; j < 8; j++)
            #pragma unroll
            for (int d = 0; d < 4; d++) acc[i][j][d] = 0.f;

    mma_1p(acc, su + OFF_SUP, bufBase, r0, c0, lane);

    // epilogue: relu(h1 + b1) contracted with W2 -> zacc
    float zacc[4][4];
    #pragma unroll
    for (int s = 0; s < 4; s++)
        #pragma unroll
        for (int o = 0; o < 4; o++) zacc[s][o] = 0.f;
    {
        int gcol = (lane & 3) * 2;
        #pragma unroll
        for (int i = 0; i < 2; i++) {
            #pragma unroll
            for (int j = 0; j < 8; j++) {
                int h = half * 128 + c0 + j * 8 + gcol;
                float b1a = s_b1[h], b1b = s_b1[h + 1];
                float4 wa = *(const float4*)&s_w2[h * 4];
                float4 wb = *(const float4*)&s_w2[(h + 1) * 4];
                float v0 = fmaxf(acc[i][j][0] + b1a, 0.f);
                float v1 = fmaxf(acc[i][j][1] + b1b, 0.f);
                float v2 = fmaxf(acc[i][j][2] + b1a, 0.f);
                float v3 = fmaxf(acc[i][j][3] + b1b, 0.f);
                zacc[i*2+0][0] += v0 * wa.x + v1 * wb.x;
                zacc[i*2+0][1] += v0 * wa.y + v1 * wb.y;
                zacc[i*2+0][2] += v0 * wa.z + v1 * wb.z;
                zacc[i*2+0][3] += v0 * wa.w + v1 * wb.w;
                zacc[i*2+1][0] += v2 * wa.x + v3 * wb.x;
                zacc[i*2+1][1] += v2 * wa.y + v3 * wb.y;
                zacc[i*2+1][2] += v2 * wa.z + v3 * wb.z;
                zacc[i*2+1][3] += v2 * wa.w + v3 * wb.w;
            }
        }
    }
    // reduce zacc over the 4 lanes sharing the same rows (lane&3 group)
    #pragma unroll
    for (int s = 0; s < 4; s++) {
        #pragma unroll
        for (int o = 0; o < 4; o++) {
            float v = zacc[s][o];
            v += __shfl_xor_sync(0xffffffffu, v, 1);
            v += __shfl_xor_sync(0xffffffffu, v, 2);
            zacc[s][o] = v;
        }
    }
    if ((lane & 3) == 0) {
        int pidx = half * 2 + (w8 & 1);
        #pragma unroll
        for (int s = 0; s < 4; s++) {
            int rr = r0 + (s >> 1) * 16 + (lane >> 2) + (s & 1) * 8;
            #pragma unroll
            for (int o = 0; o < 4; o++)
                s_zp[(pidx * 128 + rr) * 4 + o] = zacc[s][o];
        }
    }
    __syncthreads();
    {
        int n = tid >> 2, o = tid & 3;
        s_z[n * 4 + o] = s_zp[(0 * 128 + n) * 4 + o] + s_zp[(1 * 128 + n) * 4 + o]
                       + s_zp[(2 * 128 + n) * 4 + o] + s_zp[(3 * 128 + n) * 4 + o];
    }
    __syncthreads();

    // h2 = relu(sup @ z + b2) -> flat[464]   (sup from bf16 tile)
    if (tid < NN * 4) {
        int n = tid >> 2, o = tid & 3;
        float acc2 = 0.f;
        #pragma unroll
        for (int u = 0; u < 15; u++) {
            uint4 uw = *(const uint4*)(smc + OFF_SUP + (uint32_t)((n * PITCH + u * 8) * 2));
            uint32_t wv[4] = {uw.x, uw.y, uw.z, uw.w};
            #pragma unroll
            for (int p = 0; p < 4; p++) {
                int m0 = u * 8 + p * 2;
                acc2 += bf_lo(wv[p]) * s_z[m0 * 4 + o] + bf_hi(wv[p]) * s_z[(m0 + 1) * 4 + o];
            }
        }
        s_flat[tid] = fmaxf(acc2 + b2[o], 0.f);
    }
    __syncthreads();

    // r = relu(flat @ Wr1 + br1): 464x64, 8 partials per output
    {
        int j = tid & 63, p = tid >> 6;
        int i0 = p * 58;
        float a0 = 0.f, a1 = 0.f;
        #pragma unroll 2
        for (int i = 0; i < 58; i += 2) {
            a0 += s_flat[i0 + i]     * Wr1[(size_t)(i0 + i)     * 64 + j];
            a1 += s_flat[i0 + i + 1] * Wr1[(size_t)(i0 + i + 1) * 64 + j];
        }
        s_rp[p * 64 + j] = a0 + a1;
    }
    __syncthreads();
    if (tid < 64) {
        float v = br1[tid];
        #pragma unroll
        for (int p = 0; p < 8; p++) v += s_rp[p * 64 + tid];
        s_r[tid] = fmaxf(v, 0.f);
    }
    __syncthreads();

    // logits = r @ Wr2 + br2 ; log_softmax (2 classes)
    if (tid < 64) {
        float rv = s_r[tid];
        float p0 = rv * Wr2[tid * 2 + 0];
        float p1 = rv * Wr2[tid * 2 + 1];
        #pragma unroll
        for (int m = 16; m >= 1; m >>= 1) {
            p0 += __shfl_xor_sync(0xffffffffu, p0, m);
            p1 += __shfl_xor_sync(0xffffffffu, p1, m);
        }
        if ((tid & 31) == 0) {
            s_red[(tid >> 5) * 2 + 0] = p0;
            s_red[(tid >> 5) * 2 + 1] = p1;
        }
    }
    __syncthreads();
    if (tid == 0) {
        float l0 = s_red[0] + s_red[2] + br2[0];
        float l1 = s_red[1] + s_red[3] + br2[1];
        float mx = fmaxf(l0, l1);
        float lse = mx + logf(expf(l0 - mx) + expf(l1 - mx));
        out[(size_t)b * 2 + 0] = l0 - lse;
        out[(size_t)b * 2 + 1] = l1 - lse;
    }
}

extern "C" void kernel_launch(void* const* d_in, const int* in_sizes, int n_in,
                              void* d_out, int out_size) {
    const float* x   = (const float*)d_in[0];
    const float* sup = (const float*)d_in[1];
    const float* W1  = (const float*)d_in[2];
    const float* b1  = (const float*)d_in[3];
    const float* W2  = (const float*)d_in[4];
    const float* b2  = (const float*)d_in[5];
    const float* Wr1 = (const float*)d_in[6];
    const float* br1 = (const float*)d_in[7];
    const float* Wr2 = (const float*)d_in[8];
    const float* br2 = (const float*)d_in[9];
    float* out = (float*)d_out;

    int B = in_sizes[0] / (NN * FIN);

    prep_w1<<<(2 * 128 * PITCH + 255) / 256, 256>>>(W1);

    cudaFuncSetAttribute(gcn_mma, cudaFuncAttributeMaxDynamicSharedMemorySize, SMEM_BYTES);
    gcn_mma<<<B, 512, SMEM_BYTES>>>(x, sup, W1, b1, W2, b2, Wr1, br1, Wr2, br2, out);
}

// round 7
// speedup vs baseline: 5.1202x; 1.2938x over previous
#include <cuda_runtime.h>
#include <cuda_bf16.h>
#include <cstdint>

#define NN   116
#define FIN  116
#define HIDD 256
#define PITCH 136                       // bf16 elems per tile row (272B)
#define TILE_BYTES (128 * PITCH * 2)    // 34816
#define NTHR 256

// ---- SMEM byte offsets ----
#define OFF_T1    0                        // x tile (later: tail scratch)
#define OFF_T2    TILE_BYTES               // sup tile
#define OFF_T3    (2 * TILE_BYTES)         // W1 half -> xw (re-staged per half)
#define OFF_W2    (3 * TILE_BYTES)         // 256*4 f32 = 4096
#define OFF_B1V   (OFF_W2 + 4096)          // 256 f32
#define OFF_Z     (OFF_B1V + 1024)         // 128*4 f32
#define SMEM_BYTES (OFF_Z + 2048)          // 111616 (109KB) -> 2 CTAs/SM

// tail scratch overlaid in T1 (x dead after last GEMM1)
#define OFF_ZP    OFF_T1                   // 2*128*4 f32 = 4096
#define OFF_FLAT  (OFF_ZP + 4096)          // 480 f32
#define OFF_RP    (OFF_FLAT + 1920)        // 256 f32
#define OFF_R     (OFF_RP + 1024)          // 64 f32
#define OFF_RED   (OFF_R + 256)            // 16 f32

// pre-rounded W1 tile images: [half][128 rows k=f][PITCH cols n=h'] bf16
__device__ unsigned char g_w1[2 * TILE_BYTES];

__device__ __forceinline__ uint32_t smem_u32(const void* p) {
    uint32_t a;
    asm("{ .reg .u64 t; cvta.to.shared.u64 t, %1; cvt.u32.u64 %0, t; }" : "=r"(a) : "l"(p));
    return a;
}
__device__ __forceinline__ uint32_t pack_bf16(float a, float b) {
    __nv_bfloat162 v = __float22bfloat162_rn(make_float2(a, b));
    return *(uint32_t*)&v;
}
__device__ __forceinline__ float bf_lo(uint32_t w) {
    return __bfloat162float(__ushort_as_bfloat16((unsigned short)(w & 0xffff)));
}
__device__ __forceinline__ float bf_hi(uint32_t w) {
    return __bfloat162float(__ushort_as_bfloat16((unsigned short)(w >> 16)));
}

__device__ __forceinline__ void cpasync16(uint32_t s, const void* g) {
    asm volatile("cp.async.cg.shared.global [%0], [%1], 16;" :: "r"(s), "l"(g));
}
#define CP_COMMIT() asm volatile("cp.async.commit_group;")
#define CP_WAIT0()  asm volatile("cp.async.wait_group 0;")

#define LDSM_X4(r0, r1, r2, r3, addr) \
    asm volatile("ldmatrix.sync.aligned.m8n8.x4.shared.b16 {%0,%1,%2,%3}, [%4];" \
        : "=r"(r0), "=r"(r1), "=r"(r2), "=r"(r3) : "r"(addr))
#define LDSM_X4T(r0, r1, r2, r3, addr) \
    asm volatile("ldmatrix.sync.aligned.m8n8.x4.trans.shared.b16 {%0,%1,%2,%3}, [%4];" \
        : "=r"(r0), "=r"(r1), "=r"(r2), "=r"(r3) : "r"(addr))

__device__ __forceinline__ void mma16816(float* d, uint32_t a0, uint32_t a1,
                                         uint32_t a2, uint32_t a3,
                                         uint32_t b0, uint32_t b1) {
    asm volatile(
        "mma.sync.aligned.m16n8k16.row.col.f32.bf16.bf16.f32 "
        "{%0,%1,%2,%3}, {%4,%5,%6,%7}, {%8,%9}, {%0,%1,%2,%3};"
        : "+f"(d[0]), "+f"(d[1]), "+f"(d[2]), "+f"(d[3])
        : "r"(a0), "r"(a1), "r"(a2), "r"(a3), "r"(b0), "r"(b1));
}

// 1-product GEMM: acc[2][8][4] += A * B.  Warp tile: rows [r0,r0+32), cols [c0,c0+64).
__device__ __forceinline__ void mma_1p(float acc[2][8][4],
                                       uint32_t aBase, uint32_t bBase,
                                       int r0, int c0, int lane) {
    const int row_in = (lane & 7) | (((lane >> 3) & 1) << 3);
    const int col_in = (lane >> 4) << 3;
    uint32_t aA = aBase + (uint32_t)(((r0 + row_in) * PITCH + col_in) * 2);
    uint32_t bB = bBase + (uint32_t)((row_in * PITCH + c0 + col_in) * 2);
    #pragma unroll
    for (int k = 0; k < 8; ++k) {
        uint32_t a0, a1, a2, a3, a4, a5, a6, a7;
        LDSM_X4(a0, a1, a2, a3, aA);
        LDSM_X4(a4, a5, a6, a7, aA + 16 * PITCH * 2);
        #pragma unroll
        for (int jj = 0; jj < 2; ++jj) {
            uint32_t p0, p1, p2, p3, q0, q1, q2, q3;
            LDSM_X4T(p0, p1, p2, p3, bB + jj * 64);
            LDSM_X4T(q0, q1, q2, q3, bB + jj * 64 + 32);
            mma16816(acc[0][jj * 4 + 0], a0, a1, a2, a3, p0, p1);
            mma16816(acc[0][jj * 4 + 1], a0, a1, a2, a3, p2, p3);
            mma16816(acc[0][jj * 4 + 2], a0, a1, a2, a3, q0, q1);
            mma16816(acc[0][jj * 4 + 3], a0, a1, a2, a3, q2, q3);
            mma16816(acc[1][jj * 4 + 0], a4, a5, a6, a7, p0, p1);
            mma16816(acc[1][jj * 4 + 1], a4, a5, a6, a7, p2, p3);
            mma16816(acc[1][jj * 4 + 2], a4, a5, a6, a7, q0, q1);
            mma16816(acc[1][jj * 4 + 3], a4, a5, a6, a7, q2, q3);
        }
        aA += 32;                  // +16 k-cols
        bB += 16 * PITCH * 2;      // +16 k-rows
    }
}

// ---- prep: round W1 into padded global bf16 tile images (idempotent) ----
__global__ void prep_w1(const float* __restrict__ W1) {
    int idx = blockIdx.x * blockDim.x + threadIdx.x;
    if (idx >= 2 * 128 * PITCH) return;
    int half = idx / (128 * PITCH);
    int rem  = idx % (128 * PITCH);
    int r = rem / PITCH, c = rem % PITCH;     // r = f (K), c = h' (N)
    float v = (r < FIN && c < 128) ? W1[r * HIDD + half * 128 + c] : 0.f;
    *(__nv_bfloat16*)(g_w1 + half * TILE_BYTES + (size_t)rem * 2) = __float2bfloat16_rn(v);
}

extern __shared__ char smc[];

__global__ void __launch_bounds__(NTHR, 2) gcn_mma(
    const float* __restrict__ x,   const float* __restrict__ sup,
    const float* __restrict__ W1,  const float* __restrict__ b1,
    const float* __restrict__ W2,  const float* __restrict__ b2,
    const float* __restrict__ Wr1, const float* __restrict__ br1,
    const float* __restrict__ Wr2, const float* __restrict__ br2,
    float* __restrict__ out)
{
    const int tid  = threadIdx.x;
    const int b    = blockIdx.x;
    const int lane = tid & 31;
    const int warp = tid >> 5;            // 0..7
    const int r0   = (warp >> 1) * 32;    // 4 row blocks
    const int c0   = (warp & 1) * 64;     // 2 col blocks of 64

    float* s_w2   = (float*)(smc + OFF_W2);
    float* s_b1   = (float*)(smc + OFF_B1V);
    float* s_z    = (float*)(smc + OFF_Z);
    float* s_zp   = (float*)(smc + OFF_ZP);
    float* s_flat = (float*)(smc + OFF_FLAT);
    float* s_rp   = (float*)(smc + OFF_RP);
    float* s_r    = (float*)(smc + OFF_R);
    float* s_red  = (float*)(smc + OFF_RED);

    const uint32_t su = smem_u32(smc);

    // prefetch W1 half0 into T3 via cp.async — overlaps zero/convert below
    for (int i = tid; i < TILE_BYTES / 16; i += NTHR)
        cpasync16(su + OFF_T3 + i * 16, g_w1 + i * 16);
    CP_COMMIT();

    // zero x/sup tiles (pads must be 0) + preload small weights
    for (int i = tid; i < (2 * TILE_BYTES) / 16; i += NTHR)
        ((uint4*)(smc + OFF_T1))[i] = make_uint4(0, 0, 0, 0);
    for (int i = tid; i < HIDD * 4; i += NTHR) s_w2[i] = W2[i];
    for (int i = tid; i < HIDD; i += NTHR)     s_b1[i] = b1[i];
    __syncthreads();

    // load + convert x[b], sup[b] -> single bf16 tiles [m][k], pitch 136
    const float* xb = x   + (size_t)b * NN * FIN;
    const float* sb = sup + (size_t)b * NN * NN;
    for (int q = tid; q < NN * 29; q += NTHR) {
        int m = q / 29, c4 = (q % 29) * 4;
        uint32_t off = (uint32_t)((m * PITCH + c4) * 2);
        float4 vx = *(const float4*)(xb + m * FIN + c4);
        uint2 w;
        w.x = pack_bf16(vx.x, vx.y);
        w.y = pack_bf16(vx.z, vx.w);
        *(uint2*)(smc + OFF_T1 + off) = w;
        float4 vs = *(const float4*)(sb + m * NN + c4);
        w.x = pack_bf16(vs.x, vs.y);
        w.y = pack_bf16(vs.z, vs.w);
        *(uint2*)(smc + OFF_T2 + off) = w;
    }
    CP_WAIT0();
    __syncthreads();

    float zacc[4][4];
    #pragma unroll
    for (int s = 0; s < 4; s++)
        #pragma unroll
        for (int o = 0; o < 4; o++) zacc[s][o] = 0.f;

    for (int half = 0; half < 2; ++half) {
        // ---- GEMM1: xw_half = x @ W1half (A = T1, B = T3) ----
        float acc[2][8][4];
        #pragma unroll
        for (int i = 0; i < 2; i++)
            #pragma unroll
            for (int j = 0; j < 8; j++)
                #pragma unroll
                for (int d = 0; d < 4; d++) acc[i][j][d] = 0.f;

        mma_1p(acc, su + OFF_T1, su + OFF_T3, r0, c0, lane);
        __syncthreads();   // all W1 reads done before overwrite

        // store xw as bf16 into T3 ([m][h'] layout = B of GEMM2)
        {
            int grow = lane >> 2, gcol = (lane & 3) * 2;
            #pragma unroll
            for (int i = 0; i < 2; i++) {
                #pragma unroll
                for (int j = 0; j < 8; j++) {
                    int rr = r0 + i * 16 + grow;
                    int cc = c0 + j * 8 + gcol;
                    *(uint32_t*)(smc + OFF_T3 + (uint32_t)((rr * PITCH + cc) * 2)) =
                        pack_bf16(acc[i][j][0], acc[i][j][1]);
                    *(uint32_t*)(smc + OFF_T3 + (uint32_t)(((rr + 8) * PITCH + cc) * 2)) =
                        pack_bf16(acc[i][j][2], acc[i][j][3]);
                }
            }
        }
        __syncthreads();

        // ---- GEMM2: h1_half = sup @ xw_half (A = T2, B = T3) ----
        #pragma unroll
        for (int i = 0; i < 2; i++)
            #pragma unroll
            for (int j = 0; j < 8; j++)
                #pragma unroll
                for (int d = 0; d < 4; d++) acc[i][j][d] = 0.f;

        mma_1p(acc, su + OFF_T2, su + OFF_T3, r0, c0, lane);

        // epilogue: relu(h1 + b1) contracted with W2 -> zacc (registers)
        {
            int gcol = (lane & 3) * 2;
            #pragma unroll
            for (int i = 0; i < 2; i++) {
                #pragma unroll
                for (int j = 0; j < 8; j++) {
                    int h = half * 128 + c0 + j * 8 + gcol;
                    float b1a = s_b1[h], b1b = s_b1[h + 1];
                    float4 wa = *(const float4*)&s_w2[h * 4];
                    float4 wb = *(const float4*)&s_w2[(h + 1) * 4];
                    float v0 = fmaxf(acc[i][j][0] + b1a, 0.f);
                    float v1 = fmaxf(acc[i][j][1] + b1b, 0.f);
                    float v2 = fmaxf(acc[i][j][2] + b1a, 0.f);
                    float v3 = fmaxf(acc[i][j][3] + b1b, 0.f);
                    zacc[i*2+0][0] += v0 * wa.x + v1 * wb.x;
                    zacc[i*2+0][1] += v0 * wa.y + v1 * wb.y;
                    zacc[i*2+0][2] += v0 * wa.z + v1 * wb.z;
                    zacc[i*2+0][3] += v0 * wa.w + v1 * wb.w;
                    zacc[i*2+1][0] += v2 * wa.x + v3 * wb.x;
                    zacc[i*2+1][1] += v2 * wa.y + v3 * wb.y;
                    zacc[i*2+1][2] += v2 * wa.z + v3 * wb.z;
                    zacc[i*2+1][3] += v2 * wa.w + v3 * wb.w;
                }
            }
        }

        // restage W1 half1 into T3 (xw0 fully consumed)
        if (half == 0) {
            __syncthreads();
            for (int i = tid; i < TILE_BYTES / 16; i += NTHR)
                cpasync16(su + OFF_T3 + i * 16, g_w1 + TILE_BYTES + i * 16);
            CP_COMMIT();
            CP_WAIT0();
            __syncthreads();
        }
    }
    __syncthreads();   // T1/T3 reads all done; T1 becomes tail scratch

    // reduce zacc over the 4 lanes sharing the same rows (lane&3 group)
    #pragma unroll
    for (int s = 0; s < 4; s++) {
        #pragma unroll
        for (int o = 0; o < 4; o++) {
            float v = zacc[s][o];
            v += __shfl_xor_sync(0xffffffffu, v, 1);
            v += __shfl_xor_sync(0xffffffffu, v, 2);
            zacc[s][o] = v;
        }
    }
    if ((lane & 3) == 0) {
        int pidx = warp & 1;
        #pragma unroll
        for (int s = 0; s < 4; s++) {
            int rr = r0 + (s >> 1) * 16 + (lane >> 2) + (s & 1) * 8;
            #pragma unroll
            for (int o = 0; o < 4; o++)
                s_zp[(pidx * 128 + rr) * 4 + o] = zacc[s][o];
        }
    }
    __syncthreads();
    for (int q = tid; q < 512; q += NTHR) {
        int n = q >> 2, o = q & 3;
        s_z[n * 4 + o] = s_zp[(0 * 128 + n) * 4 + o] + s_zp[(1 * 128 + n) * 4 + o];
    }
    __syncthreads();

    // h2 = relu(sup @ z + b2) -> flat[464]   (sup from bf16 tile T2)
    for (int q = tid; q < NN * 4; q += NTHR) {
        int n = q >> 2, o = q & 3;
        float acc2 = 0.f;
        #pragma unroll
        for (int u = 0; u < 15; u++) {
            uint4 uw = *(const uint4*)(smc + OFF_T2 + (uint32_t)((n * PITCH + u * 8) * 2));
            uint32_t wv[4] = {uw.x, uw.y, uw.z, uw.w};
            #pragma unroll
            for (int p = 0; p < 4; p++) {
                int m0 = u * 8 + p * 2;
                acc2 += bf_lo(wv[p]) * s_z[m0 * 4 + o] + bf_hi(wv[p]) * s_z[(m0 + 1) * 4 + o];
            }
        }
        s_flat[q] = fmaxf(acc2 + b2[o], 0.f);
    }
    __syncthreads();

    // r = relu(flat @ Wr1 + br1): 464x64, 4 partials per output, 4-way chains
    {
        int j = tid & 63, p = tid >> 6;   // p in 0..3, 116 rows each
        int i0 = p * 116;
        float a0 = 0.f, a1 = 0.f, a2 = 0.f, a3 = 0.f;
        #pragma unroll 2
        for (int i = 0; i < 116; i += 4) {
            a0 += s_flat[i0 + i]     * Wr1[(size_t)(i0 + i)     * 64 + j];
            a1 += s_flat[i0 + i + 1] * Wr1[(size_t)(i0 + i + 1) * 64 + j];
            a2 += s_flat[i0 + i + 2] * Wr1[(size_t)(i0 + i + 2) * 64 + j];
            a3 += s_flat[i0 + i + 3] * Wr1[(size_t)(i0 + i + 3) * 64 + j];
        }
        s_rp[p * 64 + j] = (a0 + a1) + (a2 + a3);
    }
    __syncthreads();
    if (tid < 64) {
        float v = br1[tid] + s_rp[tid] + s_rp[64 + tid] + s_rp[128 + tid] + s_rp[192 + tid];
        s_r[tid] = fmaxf(v, 0.f);
    }
    __syncthreads();

    // logits = r @ Wr2 + br2 ; log_softmax (2 classes)
    if (tid < 64) {
        float rv = s_r[tid];
        float p0 = rv * Wr2[tid * 2 + 0];
        float p1 = rv * Wr2[tid * 2 + 1];
        #pragma unroll
        for (int m = 16; m >= 1; m >>= 1) {
            p0 += __shfl_xor_sync(0xffffffffu, p0, m);
            p1 += __shfl_xor_sync(0xffffffffu, p1, m);
        }
        if ((tid & 31) == 0) {
            s_red[(tid >> 5) * 2 + 0] = p0;
            s_red[(tid >> 5) * 2 + 1] = p1;
        }
    }
    __syncthreads();
    if (tid == 0) {
        float l0 = s_red[0] + s_red[2] + br2[0];
        float l1 = s_red[1] + s_red[3] + br2[1];
        float mx = fmaxf(l0, l1);
        float lse = mx + logf(expf(l0 - mx) + expf(l1 - mx));
        out[(size_t)b * 2 + 0] = l0 - lse;
        out[(size_t)b * 2 + 1] = l1 - lse;
    }
}

extern "C" void kernel_launch(void* const* d_in, const int* in_sizes, int n_in,
                              void* d_out, int out_size) {
    const float* x   = (const float*)d_in[0];
    const float* sup = (const float*)d_in[1];
    const float* W1  = (const float*)d_in[2];
    const float* b1  = (const float*)d_in[3];
    const float* W2  = (const float*)d_in[4];
    const float* b2  = (const float*)d_in[5];
    const float* Wr1 = (const float*)d_in[6];
    const float* br1 = (const float*)d_in[7];
    const float* Wr2 = (const float*)d_in[8];
    const float* br2 = (const float*)d_in[9];
    float* out = (float*)d_out;

    int B = in_sizes[0] / (NN * FIN);

    prep_w1<<<(2 * 128 * PITCH + 255) / 256, 256>>>(W1);

    cudaFuncSetAttribute(gcn_mma, cudaFuncAttributeMaxDynamicSharedMemorySize, SMEM_BYTES);
    gcn_mma<<<B, NTHR, SMEM_BYTES>>>(x, sup, W1, b1, W2, b2, Wr1, br1, Wr2, br2, out);
}

// round 8
// speedup vs baseline: 5.2947x; 1.0341x over previous
#include <cuda_runtime.h>
#include <cuda_bf16.h>
#include <cstdint>

#define NN   116
#define FIN  116
#define HIDD 256
#define RB   256                        // tile row bytes (128 bf16)
#define TILEB (128 * RB)                // 32768
#define NTHR 512

// swizzle for 256B-pitch tiles: spreads row%8 across banks, keeps 16B units
#define SWZ(o) ((uint32_t)(o) ^ (((uint32_t)(o) >> 4) & 0x70u))

// ---- SMEM byte offsets (per CTA total 113664 -> 2 CTAs/SM) ----
#define OFF_T1    0                        // x tile (tail scratch after GEMMs)
#define OFF_T2    TILEB                    // sup tile
#define OFF_T3    (2 * TILEB)              // W1 half -> xw (re-staged per half)
#define OFF_W2    (3 * TILEB)              // 256*4 f32 = 4096
#define OFF_B1V   (OFF_W2 + 4096)          // 256 f32
#define OFF_Z     (OFF_B1V + 1024)         // 128*4 f32 = 2048
#define OFF_ZP    (OFF_Z + 2048)           // 4*128*4 f32 = 8192 (permanent)
#define SMEM_BYTES (OFF_ZP + 8192)         // 113664

// tail scratch overlaid in T1 (x dead after last GEMM1)
#define OFF_FLAT  OFF_T1                   // 480 f32
#define OFF_RP    (OFF_FLAT + 1920)        // 512 f32
#define OFF_R     (OFF_RP + 2048)          // 64 f32
#define OFF_RED   (OFF_R + 256)            // 16 f32

// pre-rounded, pre-swizzled W1 tile images: [half][128 rows k=f][128 cols h'] bf16
__device__ unsigned char g_w1[2 * TILEB];

__device__ __forceinline__ uint32_t smem_u32(const void* p) {
    uint32_t a;
    asm("{ .reg .u64 t; cvta.to.shared.u64 t, %1; cvt.u32.u64 %0, t; }" : "=r"(a) : "l"(p));
    return a;
}
__device__ __forceinline__ uint32_t pack_bf16(float a, float b) {
    __nv_bfloat162 v = __float22bfloat162_rn(make_float2(a, b));
    return *(uint32_t*)&v;
}
__device__ __forceinline__ float bf_lo(uint32_t w) {
    return __bfloat162float(__ushort_as_bfloat16((unsigned short)(w & 0xffff)));
}
__device__ __forceinline__ float bf_hi(uint32_t w) {
    return __bfloat162float(__ushort_as_bfloat16((unsigned short)(w >> 16)));
}

__device__ __forceinline__ void cpasync16(uint32_t s, const void* g) {
    asm volatile("cp.async.cg.shared.global [%0], [%1], 16;" :: "r"(s), "l"(g));
}
#define CP_COMMIT() asm volatile("cp.async.commit_group;")
#define CP_WAIT0()  asm volatile("cp.async.wait_group 0;")

#define LDSM_X4(r0, r1, r2, r3, addr) \
    asm volatile("ldmatrix.sync.aligned.m8n8.x4.shared.b16 {%0,%1,%2,%3}, [%4];" \
        : "=r"(r0), "=r"(r1), "=r"(r2), "=r"(r3) : "r"(addr))
#define LDSM_X4T(r0, r1, r2, r3, addr) \
    asm volatile("ldmatrix.sync.aligned.m8n8.x4.trans.shared.b16 {%0,%1,%2,%3}, [%4];" \
        : "=r"(r0), "=r"(r1), "=r"(r2), "=r"(r3) : "r"(addr))

__device__ __forceinline__ void mma16816(float* d, uint32_t a0, uint32_t a1,
                                         uint32_t a2, uint32_t a3,
                                         uint32_t b0, uint32_t b1) {
    asm volatile(
        "mma.sync.aligned.m16n8k16.row.col.f32.bf16.bf16.f32 "
        "{%0,%1,%2,%3}, {%4,%5,%6,%7}, {%8,%9}, {%0,%1,%2,%3};"
        : "+f"(d[0]), "+f"(d[1]), "+f"(d[2]), "+f"(d[3])
        : "r"(a0), "r"(a1), "r"(a2), "r"(a3), "r"(b0), "r"(b1));
}

// 1-product GEMM, warp tile 32x32: acc[2][4][4] += A * B (both swizzled 256B-pitch)
__device__ __forceinline__ void mma32(float acc[2][4][4],
                                      uint32_t aTile, uint32_t bTile,
                                      int r0, int c0, int lane) {
    const int row_in = (lane & 7) | (((lane >> 3) & 1) << 3);
    const int col_in = (lane >> 4) << 3;
    const uint32_t aRel0 = (uint32_t)((r0 + row_in) * RB + col_in * 2);
    const uint32_t aRel1 = aRel0 + 16 * RB;
    const uint32_t mA0 = (aRel0 >> 4) & 0x70u;
    const uint32_t mA1 = (aRel1 >> 4) & 0x70u;
    const uint32_t bRel0 = (uint32_t)(row_in * RB + (c0 + col_in) * 2);
    const uint32_t bRel1 = bRel0 + 32;
    uint32_t b0 = bTile + SWZ(bRel0);
    uint32_t b1 = bTile + SWZ(bRel1);
    #pragma unroll
    for (int k = 0; k < 8; ++k) {
        const uint32_t ca = (uint32_t)(k * 32);
        uint32_t a0, a1, a2, a3, a4, a5, a6, a7;
        LDSM_X4(a0, a1, a2, a3, aTile + ((aRel0 + ca) ^ mA0));
        LDSM_X4(a4, a5, a6, a7, aTile + ((aRel1 + ca) ^ mA1));
        uint32_t p0, p1, p2, p3, q0, q1, q2, q3;
        LDSM_X4T(p0, p1, p2, p3, b0);
        LDSM_X4T(q0, q1, q2, q3, b1);
        mma16816(acc[0][0], a0, a1, a2, a3, p0, p1);
        mma16816(acc[0][1], a0, a1, a2, a3, p2, p3);
        mma16816(acc[0][2], a0, a1, a2, a3, q0, q1);
        mma16816(acc[0][3], a0, a1, a2, a3, q2, q3);
        mma16816(acc[1][0], a4, a5, a6, a7, p0, p1);
        mma16816(acc[1][1], a4, a5, a6, a7, p2, p3);
        mma16816(acc[1][2], a4, a5, a6, a7, q0, q1);
        mma16816(acc[1][3], a4, a5, a6, a7, q2, q3);
        b0 += 16 * RB;      // +16 k-rows (mask bits invariant)
        b1 += 16 * RB;
    }
}

// ---- prep: round W1 into pre-swizzled global bf16 tile images (idempotent) ----
__global__ void prep_w1(const float* __restrict__ W1) {
    int idx = blockIdx.x * blockDim.x + threadIdx.x;
    if (idx >= 2 * 128 * 128) return;
    int half = idx >> 14;
    int rem  = idx & 16383;
    int r = rem >> 7, c = rem & 127;          // r = f (K), c = h' (N)
    float v = (r < FIN) ? W1[r * HIDD + half * 128 + c] : 0.f;
    uint32_t off = SWZ((uint32_t)(r * RB + c * 2));
    *(__nv_bfloat16*)(g_w1 + half * TILEB + off) = __float2bfloat16_rn(v);
}

extern __shared__ char smc[];

__global__ void __launch_bounds__(NTHR, 2) gcn_mma(
    const float* __restrict__ x,   const float* __restrict__ sup,
    const float* __restrict__ W1,  const float* __restrict__ b1,
    const float* __restrict__ W2,  const float* __restrict__ b2,
    const float* __restrict__ Wr1, const float* __restrict__ br1,
    const float* __restrict__ Wr2, const float* __restrict__ br2,
    float* __restrict__ out)
{
    const int tid  = threadIdx.x;
    const int b    = blockIdx.x;
    const int lane = tid & 31;
    const int warp = tid >> 5;            // 0..15
    const int r0   = (warp >> 2) * 32;    // 4 row blocks
    const int c0   = (warp & 3) * 32;     // 4 col blocks
    const int wc   = warp & 3;

    float* s_w2   = (float*)(smc + OFF_W2);
    float* s_b1   = (float*)(smc + OFF_B1V);
    float* s_z    = (float*)(smc + OFF_Z);
    float* s_zp   = (float*)(smc + OFF_ZP);
    float* s_flat = (float*)(smc + OFF_FLAT);
    float* s_rp   = (float*)(smc + OFF_RP);
    float* s_r    = (float*)(smc + OFF_R);
    float* s_red  = (float*)(smc + OFF_RED);

    const uint32_t su = smem_u32(smc);

    // prefetch W1 half0 into T3 via cp.async — overlaps zero/convert below
    for (int i = tid; i < TILEB / 16; i += NTHR)
        cpasync16(su + OFF_T3 + i * 16, g_w1 + i * 16);
    CP_COMMIT();

    // zero x/sup tiles + zp + preload small weights
    for (int i = tid; i < (2 * TILEB) / 16; i += NTHR)
        ((uint4*)(smc + OFF_T1))[i] = make_uint4(0, 0, 0, 0);
    for (int i = tid; i < 2048; i += NTHR) s_zp[i] = 0.f;
    for (int i = tid; i < HIDD * 4; i += NTHR) s_w2[i] = W2[i];
    for (int i = tid; i < HIDD; i += NTHR)     s_b1[i] = b1[i];
    __syncthreads();

    // load + convert x[b], sup[b] -> bf16 swizzled tiles [m][k]
    const float* xb = x   + (size_t)b * NN * FIN;
    const float* sb = sup + (size_t)b * NN * NN;
    for (int q = tid; q < NN * 29; q += NTHR) {
        int m = q / 29, c4 = (q % 29) * 4;
        uint32_t off = SWZ((uint32_t)(m * RB + c4 * 2));
        float4 vx = *(const float4*)(xb + m * FIN + c4);
        uint2 w;
        w.x = pack_bf16(vx.x, vx.y);
        w.y = pack_bf16(vx.z, vx.w);
        *(uint2*)(smc + OFF_T1 + off) = w;
        float4 vs = *(const float4*)(sb + m * NN + c4);
        w.x = pack_bf16(vs.x, vs.y);
        w.y = pack_bf16(vs.z, vs.w);
        *(uint2*)(smc + OFF_T2 + off) = w;
    }
    CP_WAIT0();
    __syncthreads();

    for (int half = 0; half < 2; ++half) {
        // ---- GEMM1: xw_half = x @ W1half (A = T1, B = T3) ----
        float acc[2][4][4];
        #pragma unroll
        for (int i = 0; i < 2; i++)
            #pragma unroll
            for (int j = 0; j < 4; j++)
                #pragma unroll
                for (int d = 0; d < 4; d++) acc[i][j][d] = 0.f;

        mma32(acc, su + OFF_T1, su + OFF_T3, r0, c0, lane);
        __syncthreads();   // all W1 reads done before overwrite

        // store xw as bf16 into T3 ([m][h'] layout = B of GEMM2)
        {
            int grow = lane >> 2, gcol = (lane & 3) * 2;
            #pragma unroll
            for (int i = 0; i < 2; i++) {
                #pragma unroll
                for (int j = 0; j < 4; j++) {
                    int rr = r0 + i * 16 + grow;
                    int cc = c0 + j * 8 + gcol;
                    *(uint32_t*)(smc + OFF_T3 + SWZ((uint32_t)(rr * RB + cc * 2))) =
                        pack_bf16(acc[i][j][0], acc[i][j][1]);
                    *(uint32_t*)(smc + OFF_T3 + SWZ((uint32_t)((rr + 8) * RB + cc * 2))) =
                        pack_bf16(acc[i][j][2], acc[i][j][3]);
                }
            }
        }
        __syncthreads();

        // ---- GEMM2: h1_half = sup @ xw_half (A = T2, B = T3) ----
        #pragma unroll
        for (int i = 0; i < 2; i++)
            #pragma unroll
            for (int j = 0; j < 4; j++)
                #pragma unroll
                for (int d = 0; d < 4; d++) acc[i][j][d] = 0.f;

        mma32(acc, su + OFF_T2, su + OFF_T3, r0, c0, lane);

        // epilogue: relu(h1 + b1) contracted with W2 -> zacc -> s_zp
        {
            float zacc[4][4];
            #pragma unroll
            for (int s = 0; s < 4; s++)
                #pragma unroll
                for (int o = 0; o < 4; o++) zacc[s][o] = 0.f;
            int gcol = (lane & 3) * 2;
            #pragma unroll
            for (int i = 0; i < 2; i++) {
                #pragma unroll
                for (int j = 0; j < 4; j++) {
                    int h = half * 128 + c0 + j * 8 + gcol;
                    float b1a = s_b1[h], b1b = s_b1[h + 1];
                    float4 wa = *(const float4*)&s_w2[h * 4];
                    float4 wb = *(const float4*)&s_w2[(h + 1) * 4];
                    float v0 = fmaxf(acc[i][j][0] + b1a, 0.f);
                    float v1 = fmaxf(acc[i][j][1] + b1b, 0.f);
                    float v2 = fmaxf(acc[i][j][2] + b1a, 0.f);
                    float v3 = fmaxf(acc[i][j][3] + b1b, 0.f);
                    zacc[i*2+0][0] += v0 * wa.x + v1 * wb.x;
                    zacc[i*2+0][1] += v0 * wa.y + v1 * wb.y;
                    zacc[i*2+0][2] += v0 * wa.z + v1 * wb.z;
                    zacc[i*2+0][3] += v0 * wa.w + v1 * wb.w;
                    zacc[i*2+1][0] += v2 * wa.x + v3 * wb.x;
                    zacc[i*2+1][1] += v2 * wa.y + v3 * wb.y;
                    zacc[i*2+1][2] += v2 * wa.z + v3 * wb.z;
                    zacc[i*2+1][3] += v2 * wa.w + v3 * wb.w;
                }
            }
            // reduce over the 4 lanes sharing the same rows, accumulate to zp
            #pragma unroll
            for (int s = 0; s < 4; s++) {
                #pragma unroll
                for (int o = 0; o < 4; o++) {
                    float v = zacc[s][o];
                    v += __shfl_xor_sync(0xffffffffu, v, 1);
                    v += __shfl_xor_sync(0xffffffffu, v, 2);
                    zacc[s][o] = v;
                }
            }
            if ((lane & 3) == 0) {
                #pragma unroll
                for (int s = 0; s < 4; s++) {
                    int rr = r0 + (s >> 1) * 16 + (lane >> 2) + (s & 1) * 8;
                    #pragma unroll
                    for (int o = 0; o < 4; o++)
                        s_zp[(wc * 128 + rr) * 4 + o] += zacc[s][o];
                }
            }
        }

        // restage W1 half1 into T3 (xw0 fully consumed)
        if (half == 0) {
            __syncthreads();
            for (int i = tid; i < TILEB / 16; i += NTHR)
                cpasync16(su + OFF_T3 + i * 16, g_w1 + TILEB + i * 16);
            CP_COMMIT();
            CP_WAIT0();
            __syncthreads();
        }
    }
    __syncthreads();   // GEMMs done; T1 becomes tail scratch

    // z[n][o] = sum over the 4 column-group partials
    {
        int n = tid >> 2, o = tid & 3;   // exactly 512 items
        s_z[n * 4 + o] = s_zp[(0 * 128 + n) * 4 + o] + s_zp[(1 * 128 + n) * 4 + o]
                       + s_zp[(2 * 128 + n) * 4 + o] + s_zp[(3 * 128 + n) * 4 + o];
    }
    __syncthreads();

    // h2 = relu(sup @ z + b2) -> flat[464]   (sup from bf16 tile T2)
    if (tid < NN * 4) {
        int n = tid >> 2, o = tid & 3;
        float acc2 = 0.f;
        #pragma unroll
        for (int u = 0; u < 16; u++) {
            uint4 uw = *(const uint4*)(smc + OFF_T2 + SWZ((uint32_t)(n * RB + u * 16)));
            uint32_t wv[4] = {uw.x, uw.y, uw.z, uw.w};
            #pragma unroll
            for (int p = 0; p < 4; p++) {
                int m0 = u * 8 + p * 2;
                acc2 += bf_lo(wv[p]) * s_z[m0 * 4 + o] + bf_hi(wv[p]) * s_z[(m0 + 1) * 4 + o];
            }
        }
        s_flat[tid] = fmaxf(acc2 + b2[o], 0.f);
    }
    __syncthreads();

    // r = relu(flat @ Wr1 + br1): 464x64, 8 partials per output
    {
        int j = tid & 63, p = tid >> 6;   // p in 0..7, 58 rows each
        int i0 = p * 58;
        float a0 = 0.f, a1 = 0.f;
        #pragma unroll 2
        for (int i = 0; i < 58; i += 2) {
            a0 += s_flat[i0 + i]     * Wr1[(size_t)(i0 + i)     * 64 + j];
            a1 += s_flat[i0 + i + 1] * Wr1[(size_t)(i0 + i + 1) * 64 + j];
        }
        s_rp[p * 64 + j] = a0 + a1;
    }
    __syncthreads();
    if (tid < 64) {
        float v = br1[tid];
        #pragma unroll
        for (int p = 0; p < 8; p++) v += s_rp[p * 64 + tid];
        s_r[tid] = fmaxf(v, 0.f);
    }
    __syncthreads();

    // logits = r @ Wr2 + br2 ; log_softmax (2 classes)
    if (tid < 64) {
        float rv = s_r[tid];
        float p0 = rv * Wr2[tid * 2 + 0];
        float p1 = rv * Wr2[tid * 2 + 1];
        #pragma unroll
        for (int m = 16; m >= 1; m >>= 1) {
            p0 += __shfl_xor_sync(0xffffffffu, p0, m);
            p1 += __shfl_xor_sync(0xffffffffu, p1, m);
        }
        if ((tid & 31) == 0) {
            s_red[(tid >> 5) * 2 + 0] = p0;
            s_red[(tid >> 5) * 2 + 1] = p1;
        }
    }
    __syncthreads();
    if (tid == 0) {
        float l0 = s_red[0] + s_red[2] + br2[0];
        float l1 = s_red[1] + s_red[3] + br2[1];
        float mx = fmaxf(l0, l1);
        float lse = mx + logf(expf(l0 - mx) + expf(l1 - mx));
        out[(size_t)b * 2 + 0] = l0 - lse;
        out[(size_t)b * 2 + 1] = l1 - lse;
    }
}

extern "C" void kernel_launch(void* const* d_in, const int* in_sizes, int n_in,
                              void* d_out, int out_size) {
    const float* x   = (const float*)d_in[0];
    const float* sup = (const float*)d_in[1];
    const float* W1  = (const float*)d_in[2];
    const float* b1  = (const float*)d_in[3];
    const float* W2  = (const float*)d_in[4];
    const float* b2  = (const float*)d_in[5];
    const float* Wr1 = (const float*)d_in[6];
    const float* br1 = (const float*)d_in[7];
    const float* Wr2 = (const float*)d_in[8];
    const float* br2 = (const float*)d_in[9];
    float* out = (float*)d_out;

    int B = in_sizes[0] / (NN * FIN);

    prep_w1<<<128, 256>>>(W1);

    cudaFuncSetAttribute(gcn_mma, cudaFuncAttributeMaxDynamicSharedMemorySize, SMEM_BYTES);
    gcn_mma<<<B, NTHR, SMEM_BYTES>>>(x, sup, W1, b1, W2, b2, Wr1, br1, Wr2, br2, out);
}

// round 9
// speedup vs baseline: 5.8636x; 1.1074x over previous
#include <cuda_runtime.h>
#include <cuda_bf16.h>
#include <cstdint>

#define NN   116
#define FIN  116
#define HIDD 256
#define RB   256                        // tile row bytes (128 bf16)
#define TILEB (128 * RB)                // 32768
#define NTHR 512

// swizzle for 256B-pitch tiles: spreads row%8 across banks, keeps 16B units
#define SWZ(o) ((uint32_t)(o) ^ (((uint32_t)(o) >> 4) & 0x70u))

// ---- SMEM byte offsets (per CTA total 113664 -> 2 CTAs/SM) ----
#define OFF_T1    0                        // x tile -> sx tile (tail scratch later)
#define OFF_T2    TILEB                    // sup tile
#define OFF_T3    (2 * TILEB)              // W1 half (re-staged per half)
#define OFF_W2    (3 * TILEB)              // 256*4 f32 = 4096
#define OFF_B1V   (OFF_W2 + 4096)          // 256 f32
#define OFF_Z     (OFF_B1V + 1024)         // 128*4 f32 = 2048
#define OFF_ZP    (OFF_Z + 2048)           // 4*128*4 f32 = 8192 (permanent)
#define SMEM_BYTES (OFF_ZP + 8192)         // 113664

// tail scratch overlaid in T1 (sx dead after GEMM_B)
#define OFF_FLAT  OFF_T1                   // 480 f32
#define OFF_RP    (OFF_FLAT + 1920)        // 512 f32
#define OFF_R     (OFF_RP + 2048)          // 64 f32
#define OFF_RED   (OFF_R + 256)            // 16 f32

// pre-rounded, pre-swizzled W1 tile images: [half][128 rows k=f][128 cols h'] bf16
__device__ unsigned char g_w1[2 * TILEB];

__device__ __forceinline__ uint32_t smem_u32(const void* p) {
    uint32_t a;
    asm("{ .reg .u64 t; cvta.to.shared.u64 t, %1; cvt.u32.u64 %0, t; }" : "=r"(a) : "l"(p));
    return a;
}
__device__ __forceinline__ uint32_t pack_bf16(float a, float b) {
    __nv_bfloat162 v = __float22bfloat162_rn(make_float2(a, b));
    return *(uint32_t*)&v;
}
__device__ __forceinline__ float bf_lo(uint32_t w) {
    return __bfloat162float(__ushort_as_bfloat16((unsigned short)(w & 0xffff)));
}
__device__ __forceinline__ float bf_hi(uint32_t w) {
    return __bfloat162float(__ushort_as_bfloat16((unsigned short)(w >> 16)));
}

__device__ __forceinline__ void cpasync16(uint32_t s, const void* g) {
    asm volatile("cp.async.cg.shared.global [%0], [%1], 16;" :: "r"(s), "l"(g));
}
#define CP_COMMIT() asm volatile("cp.async.commit_group;")
#define CP_WAIT0()  asm volatile("cp.async.wait_group 0;")

#define LDSM_X4(r0, r1, r2, r3, addr) \
    asm volatile("ldmatrix.sync.aligned.m8n8.x4.shared.b16 {%0,%1,%2,%3}, [%4];" \
        : "=r"(r0), "=r"(r1), "=r"(r2), "=r"(r3) : "r"(addr))
#define LDSM_X4T(r0, r1, r2, r3, addr) \
    asm volatile("ldmatrix.sync.aligned.m8n8.x4.trans.shared.b16 {%0,%1,%2,%3}, [%4];" \
        : "=r"(r0), "=r"(r1), "=r"(r2), "=r"(r3) : "r"(addr))

__device__ __forceinline__ void mma16816(float* d, uint32_t a0, uint32_t a1,
                                         uint32_t a2, uint32_t a3,
                                         uint32_t b0, uint32_t b1) {
    asm volatile(
        "mma.sync.aligned.m16n8k16.row.col.f32.bf16.bf16.f32 "
        "{%0,%1,%2,%3}, {%4,%5,%6,%7}, {%8,%9}, {%0,%1,%2,%3};"
        : "+f"(d[0]), "+f"(d[1]), "+f"(d[2]), "+f"(d[3])
        : "r"(a0), "r"(a1), "r"(a2), "r"(a3), "r"(b0), "r"(b1));
}

// 1-product GEMM, warp tile 32x32: acc[2][4][4] += A * B (both swizzled 256B-pitch)
__device__ __forceinline__ void mma32(float acc[2][4][4],
                                      uint32_t aTile, uint32_t bTile,
                                      int r0, int c0, int lane) {
    const int row_in = (lane & 7) | (((lane >> 3) & 1) << 3);
    const int col_in = (lane >> 4) << 3;
    const uint32_t aRel0 = (uint32_t)((r0 + row_in) * RB + col_in * 2);
    const uint32_t aRel1 = aRel0 + 16 * RB;
    const uint32_t mA0 = (aRel0 >> 4) & 0x70u;
    const uint32_t mA1 = (aRel1 >> 4) & 0x70u;
    const uint32_t bRel0 = (uint32_t)(row_in * RB + (c0 + col_in) * 2);
    const uint32_t bRel1 = bRel0 + 32;
    uint32_t b0 = bTile + SWZ(bRel0);
    uint32_t b1 = bTile + SWZ(bRel1);
    #pragma unroll
    for (int k = 0; k < 8; ++k) {
        const uint32_t ca = (uint32_t)(k * 32);
        uint32_t a0, a1, a2, a3, a4, a5, a6, a7;
        LDSM_X4(a0, a1, a2, a3, aTile + ((aRel0 + ca) ^ mA0));
        LDSM_X4(a4, a5, a6, a7, aTile + ((aRel1 + ca) ^ mA1));
        uint32_t p0, p1, p2, p3, q0, q1, q2, q3;
        LDSM_X4T(p0, p1, p2, p3, b0);
        LDSM_X4T(q0, q1, q2, q3, b1);
        mma16816(acc[0][0], a0, a1, a2, a3, p0, p1);
        mma16816(acc[0][1], a0, a1, a2, a3, p2, p3);
        mma16816(acc[0][2], a0, a1, a2, a3, q0, q1);
        mma16816(acc[0][3], a0, a1, a2, a3, q2, q3);
        mma16816(acc[1][0], a4, a5, a6, a7, p0, p1);
        mma16816(acc[1][1], a4, a5, a6, a7, p2, p3);
        mma16816(acc[1][2], a4, a5, a6, a7, q0, q1);
        mma16816(acc[1][3], a4, a5, a6, a7, q2, q3);
        b0 += 16 * RB;      // +16 k-rows (mask bits invariant)
        b1 += 16 * RB;
    }
}

// ---- prep: round W1 into pre-swizzled global bf16 tile images (idempotent) ----
__global__ void prep_w1(const float* __restrict__ W1) {
    int idx = blockIdx.x * blockDim.x + threadIdx.x;
    if (idx >= 2 * 128 * 128) return;
    int half = idx >> 14;
    int rem  = idx & 16383;
    int r = rem >> 7, c = rem & 127;          // r = f (K), c = h' (N)
    float v = (r < FIN) ? W1[r * HIDD + half * 128 + c] : 0.f;
    uint32_t off = SWZ((uint32_t)(r * RB + c * 2));
    *(__nv_bfloat16*)(g_w1 + half * TILEB + off) = __float2bfloat16_rn(v);
}

extern __shared__ char smc[];

__global__ void __launch_bounds__(NTHR, 2) gcn_mma(
    const float* __restrict__ x,   const float* __restrict__ sup,
    const float* __restrict__ W1,  const float* __restrict__ b1,
    const float* __restrict__ W2,  const float* __restrict__ b2,
    const float* __restrict__ Wr1, const float* __restrict__ br1,
    const float* __restrict__ Wr2, const float* __restrict__ br2,
    float* __restrict__ out)
{
    const int tid  = threadIdx.x;
    const int b    = blockIdx.x;
    const int lane = tid & 31;
    const int warp = tid >> 5;            // 0..15
    const int r0   = (warp >> 2) * 32;    // 4 row blocks
    const int c0   = (warp & 3) * 32;     // 4 col blocks
    const int wc   = warp & 3;

    float* s_w2   = (float*)(smc + OFF_W2);
    float* s_b1   = (float*)(smc + OFF_B1V);
    float* s_z    = (float*)(smc + OFF_Z);
    float* s_zp   = (float*)(smc + OFF_ZP);
    float* s_flat = (float*)(smc + OFF_FLAT);
    float* s_rp   = (float*)(smc + OFF_RP);
    float* s_r    = (float*)(smc + OFF_R);
    float* s_red  = (float*)(smc + OFF_RED);

    const uint32_t su = smem_u32(smc);

    // prefetch W1 half0 into T3 via cp.async — hidden behind convert + GEMM_A
    for (int i = tid; i < TILEB / 16; i += NTHR)
        cpasync16(su + OFF_T3 + i * 16, g_w1 + i * 16);
    CP_COMMIT();

    // zero x/sup tiles + zp + preload small weights
    for (int i = tid; i < (2 * TILEB) / 16; i += NTHR)
        ((uint4*)(smc + OFF_T1))[i] = make_uint4(0, 0, 0, 0);
    for (int i = tid; i < 2048; i += NTHR) s_zp[i] = 0.f;
    for (int i = tid; i < HIDD * 4; i += NTHR) s_w2[i] = W2[i];
    for (int i = tid; i < HIDD; i += NTHR)     s_b1[i] = b1[i];
    __syncthreads();

    // load + convert x[b], sup[b] -> bf16 swizzled tiles [m][k]
    const float* xb = x   + (size_t)b * NN * FIN;
    const float* sb = sup + (size_t)b * NN * NN;
    for (int q = tid; q < NN * 29; q += NTHR) {
        int m = q / 29, c4 = (q % 29) * 4;
        uint32_t off = SWZ((uint32_t)(m * RB + c4 * 2));
        float4 vx = *(const float4*)(xb + m * FIN + c4);
        uint2 w;
        w.x = pack_bf16(vx.x, vx.y);
        w.y = pack_bf16(vx.z, vx.w);
        *(uint2*)(smc + OFF_T1 + off) = w;
        float4 vs = *(const float4*)(sb + m * NN + c4);
        w.x = pack_bf16(vs.x, vs.y);
        w.y = pack_bf16(vs.z, vs.w);
        *(uint2*)(smc + OFF_T2 + off) = w;
    }
    __syncthreads();

    // ---- GEMM_A: sx = sup @ x  (A = T2, B = T1) ----
    {
        float acc[2][4][4];
        #pragma unroll
        for (int i = 0; i < 2; i++)
            #pragma unroll
            for (int j = 0; j < 4; j++)
                #pragma unroll
                for (int d = 0; d < 4; d++) acc[i][j][d] = 0.f;

        mma32(acc, su + OFF_T2, su + OFF_T1, r0, c0, lane);
        __syncthreads();   // all x reads done before overwrite

        // store sx as bf16 into T1 ([n][f] layout = A of GEMM_B)
        int grow = lane >> 2, gcol = (lane & 3) * 2;
        #pragma unroll
        for (int i = 0; i < 2; i++) {
            #pragma unroll
            for (int j = 0; j < 4; j++) {
                int rr = r0 + i * 16 + grow;
                int cc = c0 + j * 8 + gcol;
                *(uint32_t*)(smc + OFF_T1 + SWZ((uint32_t)(rr * RB + cc * 2))) =
                    pack_bf16(acc[i][j][0], acc[i][j][1]);
                *(uint32_t*)(smc + OFF_T1 + SWZ((uint32_t)((rr + 8) * RB + cc * 2))) =
                    pack_bf16(acc[i][j][2], acc[i][j][3]);
            }
        }
    }
    CP_WAIT0();      // W1 half0 landed
    __syncthreads();

    for (int half = 0; half < 2; ++half) {
        // ---- GEMM_B: h1_half = sx @ W1half (A = T1, B = T3) ----
        float acc[2][4][4];
        #pragma unroll
        for (int i = 0; i < 2; i++)
            #pragma unroll
            for (int j = 0; j < 4; j++)
                #pragma unroll
                for (int d = 0; d < 4; d++) acc[i][j][d] = 0.f;

        mma32(acc, su + OFF_T1, su + OFF_T3, r0, c0, lane);

        // restage W1 half1 NOW (T3 reads done after barrier); overlaps epilogue
        if (half == 0) {
            __syncthreads();   // all warps' T3 reads done
            for (int i = tid; i < TILEB / 16; i += NTHR)
                cpasync16(su + OFF_T3 + i * 16, g_w1 + TILEB + i * 16);
            CP_COMMIT();
        }

        // epilogue: relu(h1 + b1) contracted with W2 -> zacc -> s_zp
        {
            float zacc[4][4];
            #pragma unroll
            for (int s = 0; s < 4; s++)
                #pragma unroll
                for (int o = 0; o < 4; o++) zacc[s][o] = 0.f;
            int gcol = (lane & 3) * 2;
            #pragma unroll
            for (int i = 0; i < 2; i++) {
                #pragma unroll
                for (int j = 0; j < 4; j++) {
                    int h = half * 128 + c0 + j * 8 + gcol;
                    float b1a = s_b1[h], b1b = s_b1[h + 1];
                    float4 wa = *(const float4*)&s_w2[h * 4];
                    float4 wb = *(const float4*)&s_w2[(h + 1) * 4];
                    float v0 = fmaxf(acc[i][j][0] + b1a, 0.f);
                    float v1 = fmaxf(acc[i][j][1] + b1b, 0.f);
                    float v2 = fmaxf(acc[i][j][2] + b1a, 0.f);
                    float v3 = fmaxf(acc[i][j][3] + b1b, 0.f);
                    zacc[i*2+0][0] += v0 * wa.x + v1 * wb.x;
                    zacc[i*2+0][1] += v0 * wa.y + v1 * wb.y;
                    zacc[i*2+0][2] += v0 * wa.z + v1 * wb.z;
                    zacc[i*2+0][3] += v0 * wa.w + v1 * wb.w;
                    zacc[i*2+1][0] += v2 * wa.x + v3 * wb.x;
                    zacc[i*2+1][1] += v2 * wa.y + v3 * wb.y;
                    zacc[i*2+1][2] += v2 * wa.z + v3 * wb.z;
                    zacc[i*2+1][3] += v2 * wa.w + v3 * wb.w;
                }
            }
            // reduce over the 4 lanes sharing the same rows, accumulate to zp
            #pragma unroll
            for (int s = 0; s < 4; s++) {
                #pragma unroll
                for (int o = 0; o < 4; o++) {
                    float v = zacc[s][o];
                    v += __shfl_xor_sync(0xffffffffu, v, 1);
                    v += __shfl_xor_sync(0xffffffffu, v, 2);
                    zacc[s][o] = v;
                }
            }
            if ((lane & 3) == 0) {
                #pragma unroll
                for (int s = 0; s < 4; s++) {
                    int rr = r0 + (s >> 1) * 16 + (lane >> 2) + (s & 1) * 8;
                    #pragma unroll
                    for (int o = 0; o < 4; o++)
                        s_zp[(wc * 128 + rr) * 4 + o] += zacc[s][o];
                }
            }
        }

        if (half == 0) {
            CP_WAIT0();      // W1 half1 landed (copy overlapped the epilogue)
            __syncthreads();
        }
    }
    __syncthreads();   // GEMMs done; T1 becomes tail scratch

    // z[n][o] = sum over the 4 column-group partials
    {
        int n = tid >> 2, o = tid & 3;   // exactly 512 items
        s_z[n * 4 + o] = s_zp[(0 * 128 + n) * 4 + o] + s_zp[(1 * 128 + n) * 4 + o]
                       + s_zp[(2 * 128 + n) * 4 + o] + s_zp[(3 * 128 + n) * 4 + o];
    }
    __syncthreads();

    // h2 = relu(sup @ z + b2) -> flat[464]   (sup from bf16 tile T2)
    if (tid < NN * 4) {
        int n = tid >> 2, o = tid & 3;
        float acc2 = 0.f;
        #pragma unroll
        for (int u = 0; u < 16; u++) {
            uint4 uw = *(const uint4*)(smc + OFF_T2 + SWZ((uint32_t)(n * RB + u * 16)));
            uint32_t wv[4] = {uw.x, uw.y, uw.z, uw.w};
            #pragma unroll
            for (int p = 0; p < 4; p++) {
                int m0 = u * 8 + p * 2;
                acc2 += bf_lo(wv[p]) * s_z[m0 * 4 + o] + bf_hi(wv[p]) * s_z[(m0 + 1) * 4 + o];
            }
        }
        s_flat[tid] = fmaxf(acc2 + b2[o], 0.f);
    }
    __syncthreads();

    // r = relu(flat @ Wr1 + br1): 464x64, 8 partials per output
    {
        int j = tid & 63, p = tid >> 6;   // p in 0..7, 58 rows each
        int i0 = p * 58;
        float a0 = 0.f, a1 = 0.f;
        #pragma unroll 2
        for (int i = 0; i < 58; i += 2) {
            a0 += s_flat[i0 + i]     * Wr1[(size_t)(i0 + i)     * 64 + j];
            a1 += s_flat[i0 + i + 1] * Wr1[(size_t)(i0 + i + 1) * 64 + j];
        }
        s_rp[p * 64 + j] = a0 + a1;
    }
    __syncthreads();
    if (tid < 64) {
        float v = br1[tid];
        #pragma unroll
        for (int p = 0; p < 8; p++) v += s_rp[p * 64 + tid];
        s_r[tid] = fmaxf(v, 0.f);
    }
    __syncthreads();

    // logits = r @ Wr2 + br2 ; log_softmax (2 classes)
    if (tid < 64) {
        float rv = s_r[tid];
        float p0 = rv * Wr2[tid * 2 + 0];
        float p1 = rv * Wr2[tid * 2 + 1];
        #pragma unroll
        for (int m = 16; m >= 1; m >>= 1) {
            p0 += __shfl_xor_sync(0xffffffffu, p0, m);
            p1 += __shfl_xor_sync(0xffffffffu, p1, m);
        }
        if ((tid & 31) == 0) {
            s_red[(tid >> 5) * 2 + 0] = p0;
            s_red[(tid >> 5) * 2 + 1] = p1;
        }
    }
    __syncthreads();
    if (tid == 0) {
        float l0 = s_red[0] + s_red[2] + br2[0];
        float l1 = s_red[1] + s_red[3] + br2[1];
        float mx = fmaxf(l0, l1);
        float lse = mx + logf(expf(l0 - mx) + expf(l1 - mx));
        out[(size_t)b * 2 + 0] = l0 - lse;
        out[(size_t)b * 2 + 1] = l1 - lse;
    }
}

extern "C" void kernel_launch(void* const* d_in, const int* in_sizes, int n_in,
                              void* d_out, int out_size) {
    const float* x   = (const float*)d_in[0];
    const float* sup = (const float*)d_in[1];
    const float* W1  = (const float*)d_in[2];
    const float* b1  = (const float*)d_in[3];
    const float* W2  = (const float*)d_in[4];
    const float* b2  = (const float*)d_in[5];
    const float* Wr1 = (const float*)d_in[6];
    const float* br1 = (const float*)d_in[7];
    const float* Wr2 = (const float*)d_in[8];
    const float* br2 = (const float*)d_in[9];
    float* out = (float*)d_out;

    int B = in_sizes[0] / (NN * FIN);

    prep_w1<<<128, 256>>>(W1);

    cudaFuncSetAttribute(gcn_mma, cudaFuncAttributeMaxDynamicSharedMemorySize, SMEM_BYTES);
    gcn_mma<<<B, NTHR, SMEM_BYTES>>>(x, sup, W1, b1, W2, b2, Wr1, br1, Wr2, br2, out);
}